// round 1
// baseline (speedup 1.0000x reference)
#include <cuda_runtime.h>
#include <math.h>

// GraphQNN: 22-qubit real-amplitude state-vector simulation.
// state (float, 16MB) lives in a __device__ global and stays L2-resident.
// Each layer = passH (bits 14..21) + passL (bits 0..13, + sign).
// Layer-1 passH synthesizes the initial product state analytically.
// Layer-3 passL fuses the expectation-value reduction (sign^2 == 1, skipped).

#define NQ 22
#define DIM (1 << NQ)
#define LOWB 14
#define LOWDIM (1 << LOWB)

__device__ float g_state[DIM];
__device__ unsigned g_sign[DIM / 32];
__device__ float g_c[4][NQ];   // [stage][bit]  stage0 = features, 1..3 = layers
__device__ float g_s[4][NQ];
__device__ unsigned g_mask[NQ];

// ---------------------------------------------------------------- setup
__global__ void k_setup(const float* __restrict__ feat,
                        const float* __restrict__ adj,
                        const float* __restrict__ params,
                        float* __restrict__ out) {
    int t = threadIdx.x;
    if (t < 4 * NQ) {
        int s = t / NQ;
        int b = t % NQ;
        int q = NQ - 1 - b;   // bit b of the index corresponds to qubit NQ-1-b
        float th = (s == 0 ? feat[q] : params[(s - 1) * NQ + q]) * 0.5f;
        g_c[s][b] = cosf(th);
        g_s[s][b] = sinf(th);
    }
    if (t < NQ) {
        unsigned m = 0;
        for (int j = t + 1; j < NQ; j++)
            if (adj[t * NQ + j] > 0.0f) m |= (1u << (NQ - 1 - j));
        g_mask[t] = m;
        out[t] = 0.0f;   // d_out is poisoned; zero it (we accumulate atomically)
    }
}

// ---------------------------------------------------------------- sign pack
__global__ void k_sign() {
    __shared__ unsigned mk[NQ];
    int t = threadIdx.x;
    if (t < NQ) mk[t] = g_mask[t];
    __syncthreads();
    unsigned x = blockIdx.x * blockDim.x + t;
    unsigned p = 0;
#pragma unroll
    for (int i = 0; i < NQ; i++)
        p ^= ((x >> (NQ - 1 - i)) & 1u) & ((unsigned)__popc(x & mk[i]) & 1u);
    unsigned bal = __ballot_sync(0xffffffffu, p);
    if ((t & 31) == 0) g_sign[x >> 5] = bal;
}

// ---------------------------------------------------------------- butterfly
template <int BIT>
__device__ __forceinline__ void bfly16(float* r, float c, float s) {
#pragma unroll
    for (int k0 = 0; k0 < 16; k0++) {
        if ((k0 & (1 << BIT)) == 0) {
            int k1 = k0 | (1 << BIT);
            float v0 = r[k0], v1 = r[k1];
            r[k0] = fmaf(c, v0, -(s * v1));
            r[k1] = fmaf(s, v0, c * v1);
        }
    }
}

// ---------------------------------------------------------------- pass H
// Handles global bits 14..21. Tile = 256 h-values x 64 low-values (64KB smem).
// Thread t: tl = t&63 (low offset), th = t>>6 (h bits 4..7).
// Arrangement A: regs own h bits 0..3 ; exchange ; B: regs own h bits 4..7.
template <int STAGE, bool INIT>
__global__ void __launch_bounds__(1024) k_passH() {
    extern __shared__ float sm[];   // 16384 floats
    const int t = threadIdx.x;
    const int tl = t & 63;
    const int th = t >> 6;
    const int low = (blockIdx.x << 6) + tl;
    float r[16];

    if (INIT) {
        // initial product state: amp(x) = prod_b (bit_b ? sin : cos), stage 0
        float a = 1.0f;
#pragma unroll
        for (int b = 0; b < LOWB; b++)
            a *= ((low >> b) & 1) ? g_s[0][b] : g_c[0][b];
#pragma unroll
        for (int b = 0; b < 4; b++)
            a *= ((th >> b) & 1) ? g_s[0][LOWB + 4 + b] : g_c[0][LOWB + 4 + b];
#pragma unroll
        for (int k = 0; k < 16; k++) {
            float a2 = a;
#pragma unroll
            for (int b = 0; b < 4; b++)
                a2 *= ((k >> b) & 1) ? g_s[0][LOWB + b] : g_c[0][LOWB + b];
            r[k] = a2;
        }
    } else {
#pragma unroll
        for (int k = 0; k < 16; k++)
            r[k] = g_state[((th * 16 + k) << LOWB) | low];
    }

    // butterflies on h bits 0..3  (global bits 14..17)
    bfly16<0>(r, g_c[STAGE][LOWB + 0], g_s[STAGE][LOWB + 0]);
    bfly16<1>(r, g_c[STAGE][LOWB + 1], g_s[STAGE][LOWB + 1]);
    bfly16<2>(r, g_c[STAGE][LOWB + 2], g_s[STAGE][LOWB + 2]);
    bfly16<3>(r, g_c[STAGE][LOWB + 3], g_s[STAGE][LOWB + 3]);

    // exchange: [h][tl] layout, both directions conflict-free
#pragma unroll
    for (int k = 0; k < 16; k++)
        sm[((th << 4) | k) * 64 + tl] = r[k];
    __syncthreads();
#pragma unroll
    for (int k = 0; k < 16; k++)
        r[k] = sm[((k << 4) | th) * 64 + tl];

    // butterflies on h bits 4..7  (global bits 18..21)
    bfly16<0>(r, g_c[STAGE][LOWB + 4], g_s[STAGE][LOWB + 4]);
    bfly16<1>(r, g_c[STAGE][LOWB + 5], g_s[STAGE][LOWB + 5]);
    bfly16<2>(r, g_c[STAGE][LOWB + 6], g_s[STAGE][LOWB + 6]);
    bfly16<3>(r, g_c[STAGE][LOWB + 7], g_s[STAGE][LOWB + 7]);

#pragma unroll
    for (int k = 0; k < 16; k++)
        g_state[(((k << 4) | th) << LOWB) | low] = r[k];
}

// ---------------------------------------------------------------- pass L
// Handles global bits 0..13 within a contiguous 16384-element block,
// applies the diagonal sign (stages 1,2), or the fused reduction (stage 3).
__device__ __forceinline__ int swz(int a) { return a ^ ((a >> 4) & 31); }

template <int STAGE, bool LAST>
__global__ void __launch_bounds__(1024) k_passL(float* __restrict__ out) {
    extern __shared__ float sm[];   // 16384 floats
    __shared__ float acc[NQ];
    const int t = threadIdx.x;
    const int base = blockIdx.x << LOWB;
    float r[16];

    if (LAST && t < NQ) acc[t] = 0.0f;

    // arrangement 0: regs own bits 0..3 (contiguous -> float4 loads)
    const float4* gp = reinterpret_cast<const float4*>(&g_state[base + t * 16]);
    float4 q0 = gp[0], q1 = gp[1], q2 = gp[2], q3 = gp[3];
    r[0] = q0.x;  r[1] = q0.y;  r[2] = q0.z;  r[3] = q0.w;
    r[4] = q1.x;  r[5] = q1.y;  r[6] = q1.z;  r[7] = q1.w;
    r[8] = q2.x;  r[9] = q2.y;  r[10] = q2.z; r[11] = q2.w;
    r[12] = q3.x; r[13] = q3.y; r[14] = q3.z; r[15] = q3.w;

    bfly16<0>(r, g_c[STAGE][0], g_s[STAGE][0]);
    bfly16<1>(r, g_c[STAGE][1], g_s[STAGE][1]);
    bfly16<2>(r, g_c[STAGE][2], g_s[STAGE][2]);
    bfly16<3>(r, g_c[STAGE][3], g_s[STAGE][3]);

    // exchange -> regs own bits 4..7
#pragma unroll
    for (int k = 0; k < 16; k++)
        sm[swz((t << 4) | k)] = r[k];
    __syncthreads();
#pragma unroll
    for (int k = 0; k < 16; k++)
        r[k] = sm[swz(((t >> 4) << 8) | (k << 4) | (t & 15))];

    bfly16<0>(r, g_c[STAGE][4], g_s[STAGE][4]);
    bfly16<1>(r, g_c[STAGE][5], g_s[STAGE][5]);
    bfly16<2>(r, g_c[STAGE][6], g_s[STAGE][6]);
    bfly16<3>(r, g_c[STAGE][7], g_s[STAGE][7]);

#pragma unroll
    for (int k = 0; k < 16; k++)
        sm[swz(((t >> 4) << 8) | (k << 4) | (t & 15))] = r[k];
    __syncthreads();

    // regs own bits 8..11
#pragma unroll
    for (int k = 0; k < 16; k++)
        r[k] = sm[swz(((t >> 8) << 12) | (k << 8) | (t & 255))];

    bfly16<0>(r, g_c[STAGE][8], g_s[STAGE][8]);
    bfly16<1>(r, g_c[STAGE][9], g_s[STAGE][9]);
    bfly16<2>(r, g_c[STAGE][10], g_s[STAGE][10]);
    bfly16<3>(r, g_c[STAGE][11], g_s[STAGE][11]);

#pragma unroll
    for (int k = 0; k < 16; k++)
        sm[swz(((t >> 8) << 12) | (k << 8) | (t & 255))] = r[k];
    __syncthreads();

    // regs own bits 10..13 ; butterfly bits 12,13 (k bits 2,3)
#pragma unroll
    for (int k = 0; k < 16; k++)
        r[k] = sm[swz((k << 10) | t)];

    bfly16<2>(r, g_c[STAGE][12], g_s[STAGE][12]);
    bfly16<3>(r, g_c[STAGE][13], g_s[STAGE][13]);

    if (!LAST) {
        // diagonal sign then store (coalesced per-k across the warp)
#pragma unroll
        for (int k = 0; k < 16; k++) {
            int x = base | (k << 10) | t;
            unsigned w = g_sign[x >> 5];
            float v = r[k];
            if ((w >> (x & 31)) & 1) v = -v;
            g_state[x] = v;
        }
    } else {
        // fused expectation values: out[q] = sum probs * (1 - 2*bit_{21-q})
        // sign^2 == 1 so the layer-3 diagonal is skipped entirely.
        float P = 0.f, S0 = 0.f, S1 = 0.f, S2 = 0.f, S3 = 0.f;
#pragma unroll
        for (int k = 0; k < 16; k++) {
            float p = r[k] * r[k];
            P += p;                        // total prob of this thread's elems
            S0 += (k & 1) ? -p : p;        // bit 10
            S1 += (k & 2) ? -p : p;        // bit 11
            S2 += (k & 4) ? -p : p;        // bit 12
            S3 += (k & 8) ? -p : p;        // bit 13
        }
        int lane = t & 31;
        float R0 = (lane & 1)  ? -P : P;   // bit 0
        float R1 = (lane & 2)  ? -P : P;   // bit 1
        float R2 = (lane & 4)  ? -P : P;   // bit 2
        float R3 = (lane & 8)  ? -P : P;   // bit 3
        float R4 = (lane & 16) ? -P : P;   // bit 4
#pragma unroll
        for (int o = 16; o; o >>= 1) {
            P  += __shfl_xor_sync(0xffffffffu, P, o);
            S0 += __shfl_xor_sync(0xffffffffu, S0, o);
            S1 += __shfl_xor_sync(0xffffffffu, S1, o);
            S2 += __shfl_xor_sync(0xffffffffu, S2, o);
            S3 += __shfl_xor_sync(0xffffffffu, S3, o);
            R0 += __shfl_xor_sync(0xffffffffu, R0, o);
            R1 += __shfl_xor_sync(0xffffffffu, R1, o);
            R2 += __shfl_xor_sync(0xffffffffu, R2, o);
            R3 += __shfl_xor_sync(0xffffffffu, R3, o);
            R4 += __shfl_xor_sync(0xffffffffu, R4, o);
        }
        __syncthreads();   // acc[] zero visible
        if (lane == 0) {
            int wrp = t >> 5;              // bits 5..9 of the index
            atomicAdd(&acc[0], R0);
            atomicAdd(&acc[1], R1);
            atomicAdd(&acc[2], R2);
            atomicAdd(&acc[3], R3);
            atomicAdd(&acc[4], R4);
#pragma unroll
            for (int b = 5; b < 10; b++)
                atomicAdd(&acc[b], ((wrp >> (b - 5)) & 1) ? -P : P);
            atomicAdd(&acc[10], S0);
            atomicAdd(&acc[11], S1);
            atomicAdd(&acc[12], S2);
            atomicAdd(&acc[13], S3);
#pragma unroll
            for (int b = 14; b < NQ; b++)
                atomicAdd(&acc[b], ((blockIdx.x >> (b - 14)) & 1) ? -P : P);
        }
        __syncthreads();
        if (t < NQ) atomicAdd(&out[NQ - 1 - t], acc[t]);
    }
}

// ---------------------------------------------------------------- launch
extern "C" void kernel_launch(void* const* d_in, const int* in_sizes, int n_in,
                              void* d_out, int out_size) {
    const float* feat = (const float*)d_in[0];
    const float* adj = (const float*)d_in[1];
    const float* params = (const float*)d_in[2];
    float* out = (float*)d_out;

    const int SMEM = LOWDIM * (int)sizeof(float);   // 65536
    cudaFuncSetAttribute(k_passH<1, true>,  cudaFuncAttributeMaxDynamicSharedMemorySize, SMEM);
    cudaFuncSetAttribute(k_passH<2, false>, cudaFuncAttributeMaxDynamicSharedMemorySize, SMEM);
    cudaFuncSetAttribute(k_passH<3, false>, cudaFuncAttributeMaxDynamicSharedMemorySize, SMEM);
    cudaFuncSetAttribute(k_passL<1, false>, cudaFuncAttributeMaxDynamicSharedMemorySize, SMEM);
    cudaFuncSetAttribute(k_passL<2, false>, cudaFuncAttributeMaxDynamicSharedMemorySize, SMEM);
    cudaFuncSetAttribute(k_passL<3, true>,  cudaFuncAttributeMaxDynamicSharedMemorySize, SMEM);

    k_setup<<<1, 128>>>(feat, adj, params, out);
    k_sign<<<DIM / 256, 256>>>();

    k_passH<1, true><<<LOWDIM / 64, 1024, SMEM>>>();
    k_passL<1, false><<<DIM / LOWDIM, 1024, SMEM>>>(out);
    k_passH<2, false><<<LOWDIM / 64, 1024, SMEM>>>();
    k_passL<2, false><<<DIM / LOWDIM, 1024, SMEM>>>(out);
    k_passH<3, false><<<LOWDIM / 64, 1024, SMEM>>>();
    k_passL<3, true><<<DIM / LOWDIM, 1024, SMEM>>>(out);
}

// round 2
// speedup vs baseline: 1.0512x; 1.0512x over previous
#include <cuda_runtime.h>
#include <math.h>

// GraphQNN: 22-qubit real-amplitude state-vector simulation.
// state (float, 16MB) lives in a __device__ global and stays L2-resident.
// Each layer = passH (bits 14..21) + passL (bits 0..13, + sign).
// Layer-1 passH synthesizes the initial product state analytically.
// Layer-3 passL fuses the expectation-value reduction (sign^2 == 1, skipped).
//
// R2 change: __launch_bounds__(1024, 2) for 2 CTAs/SM (grid 256 -> 1 wave,
// 64 warps/SM) + stage coefficients staged through static shared memory so
// the 32-register budget holds without spilling (R1 had 51 regs -> 1 CTA/SM,
// 1.73 waves, issue 28.6%).

#define NQ 22
#define DIM (1 << NQ)
#define LOWB 14
#define LOWDIM (1 << LOWB)

__device__ float g_state[DIM];
__device__ unsigned g_sign[DIM / 32];
__device__ float g_c[4][NQ];   // [stage][bit]  stage0 = features, 1..3 = layers
__device__ float g_s[4][NQ];
__device__ unsigned g_mask[NQ];

// ---------------------------------------------------------------- setup
__global__ void k_setup(const float* __restrict__ feat,
                        const float* __restrict__ adj,
                        const float* __restrict__ params,
                        float* __restrict__ out) {
    int t = threadIdx.x;
    if (t < 4 * NQ) {
        int s = t / NQ;
        int b = t % NQ;
        int q = NQ - 1 - b;   // bit b of the index corresponds to qubit NQ-1-b
        float th = (s == 0 ? feat[q] : params[(s - 1) * NQ + q]) * 0.5f;
        g_c[s][b] = cosf(th);
        g_s[s][b] = sinf(th);
    }
    if (t < NQ) {
        unsigned m = 0;
        for (int j = t + 1; j < NQ; j++)
            if (adj[t * NQ + j] > 0.0f) m |= (1u << (NQ - 1 - j));
        g_mask[t] = m;
        out[t] = 0.0f;   // d_out is poisoned; zero it (we accumulate atomically)
    }
}

// ---------------------------------------------------------------- sign pack
__global__ void k_sign() {
    __shared__ unsigned mk[NQ];
    int t = threadIdx.x;
    if (t < NQ) mk[t] = g_mask[t];
    __syncthreads();
    unsigned x = blockIdx.x * blockDim.x + t;
    unsigned p = 0;
#pragma unroll
    for (int i = 0; i < NQ; i++)
        p ^= ((x >> (NQ - 1 - i)) & 1u) & ((unsigned)__popc(x & mk[i]) & 1u);
    unsigned bal = __ballot_sync(0xffffffffu, p);
    if ((t & 31) == 0) g_sign[x >> 5] = bal;
}

// ---------------------------------------------------------------- butterfly
template <int BIT>
__device__ __forceinline__ void bfly16(float* r, float c, float s) {
#pragma unroll
    for (int k0 = 0; k0 < 16; k0++) {
        if ((k0 & (1 << BIT)) == 0) {
            int k1 = k0 | (1 << BIT);
            float v0 = r[k0], v1 = r[k1];
            r[k0] = fmaf(c, v0, -(s * v1));
            r[k1] = fmaf(s, v0, c * v1);
        }
    }
}

// ---------------------------------------------------------------- pass H
// Handles global bits 14..21. Tile = 256 h-values x 64 low-values (64KB smem).
// Thread t: tl = t&63 (low offset), th = t>>6 (h bits 4..7).
// Arrangement A: regs own h bits 0..3 ; exchange ; B: regs own h bits 4..7.
template <int STAGE, bool INIT>
__global__ void __launch_bounds__(1024, 2) k_passH() {
    extern __shared__ float sm[];   // 16384 floats
    __shared__ float sc[NQ], ss[NQ], sc0[NQ], ss0[NQ];
    const int t = threadIdx.x;
    if (t < NQ) {
        sc[t] = g_c[STAGE][t];
        ss[t] = g_s[STAGE][t];
        if (INIT) { sc0[t] = g_c[0][t]; ss0[t] = g_s[0][t]; }
    }
    __syncthreads();

    const int tl = t & 63;
    const int th = t >> 6;
    const int low = (blockIdx.x << 6) + tl;
    float r[16];

    if (INIT) {
        // initial product state: amp(x) = prod_b (bit_b ? sin : cos), stage 0
        float a = 1.0f;
#pragma unroll
        for (int b = 0; b < LOWB; b++)
            a *= ((low >> b) & 1) ? ss0[b] : sc0[b];
#pragma unroll
        for (int b = 0; b < 4; b++)
            a *= ((th >> b) & 1) ? ss0[LOWB + 4 + b] : sc0[LOWB + 4 + b];
#pragma unroll
        for (int k = 0; k < 16; k++) {
            float a2 = a;
#pragma unroll
            for (int b = 0; b < 4; b++)
                a2 *= ((k >> b) & 1) ? ss0[LOWB + b] : sc0[LOWB + b];
            r[k] = a2;
        }
    } else {
#pragma unroll
        for (int k = 0; k < 16; k++)
            r[k] = g_state[((th * 16 + k) << LOWB) | low];
    }

    // butterflies on h bits 0..3  (global bits 14..17)
    bfly16<0>(r, sc[LOWB + 0], ss[LOWB + 0]);
    bfly16<1>(r, sc[LOWB + 1], ss[LOWB + 1]);
    bfly16<2>(r, sc[LOWB + 2], ss[LOWB + 2]);
    bfly16<3>(r, sc[LOWB + 3], ss[LOWB + 3]);

    // exchange: [h][tl] layout, both directions conflict-free
#pragma unroll
    for (int k = 0; k < 16; k++)
        sm[((th << 4) | k) * 64 + tl] = r[k];
    __syncthreads();
#pragma unroll
    for (int k = 0; k < 16; k++)
        r[k] = sm[((k << 4) | th) * 64 + tl];

    // butterflies on h bits 4..7  (global bits 18..21)
    bfly16<0>(r, sc[LOWB + 4], ss[LOWB + 4]);
    bfly16<1>(r, sc[LOWB + 5], ss[LOWB + 5]);
    bfly16<2>(r, sc[LOWB + 6], ss[LOWB + 6]);
    bfly16<3>(r, sc[LOWB + 7], ss[LOWB + 7]);

#pragma unroll
    for (int k = 0; k < 16; k++)
        g_state[(((k << 4) | th) << LOWB) | low] = r[k];
}

// ---------------------------------------------------------------- pass L
// Handles global bits 0..13 within a contiguous 16384-element block,
// applies the diagonal sign (stages 1,2), or the fused reduction (stage 3).
__device__ __forceinline__ int swz(int a) { return a ^ ((a >> 4) & 31); }

template <int STAGE, bool LAST>
__global__ void __launch_bounds__(1024, 2) k_passL(float* __restrict__ out) {
    extern __shared__ float sm[];   // 16384 floats
    __shared__ float sc[NQ], ss[NQ];
    __shared__ float acc[NQ];
    const int t = threadIdx.x;
    const int base = blockIdx.x << LOWB;
    float r[16];

    if (t < NQ) {
        sc[t] = g_c[STAGE][t];
        ss[t] = g_s[STAGE][t];
        if (LAST) acc[t] = 0.0f;
    }
    __syncthreads();

    // arrangement 0: regs own bits 0..3 (contiguous -> float4 loads)
    const float4* gp = reinterpret_cast<const float4*>(&g_state[base + t * 16]);
    float4 q0 = gp[0], q1 = gp[1], q2 = gp[2], q3 = gp[3];
    r[0] = q0.x;  r[1] = q0.y;  r[2] = q0.z;  r[3] = q0.w;
    r[4] = q1.x;  r[5] = q1.y;  r[6] = q1.z;  r[7] = q1.w;
    r[8] = q2.x;  r[9] = q2.y;  r[10] = q2.z; r[11] = q2.w;
    r[12] = q3.x; r[13] = q3.y; r[14] = q3.z; r[15] = q3.w;

    bfly16<0>(r, sc[0], ss[0]);
    bfly16<1>(r, sc[1], ss[1]);
    bfly16<2>(r, sc[2], ss[2]);
    bfly16<3>(r, sc[3], ss[3]);

    // exchange -> regs own bits 4..7
#pragma unroll
    for (int k = 0; k < 16; k++)
        sm[swz((t << 4) | k)] = r[k];
    __syncthreads();
#pragma unroll
    for (int k = 0; k < 16; k++)
        r[k] = sm[swz(((t >> 4) << 8) | (k << 4) | (t & 15))];

    bfly16<0>(r, sc[4], ss[4]);
    bfly16<1>(r, sc[5], ss[5]);
    bfly16<2>(r, sc[6], ss[6]);
    bfly16<3>(r, sc[7], ss[7]);

    __syncthreads();
#pragma unroll
    for (int k = 0; k < 16; k++)
        sm[swz(((t >> 4) << 8) | (k << 4) | (t & 15))] = r[k];
    __syncthreads();

    // regs own bits 8..11
#pragma unroll
    for (int k = 0; k < 16; k++)
        r[k] = sm[swz(((t >> 8) << 12) | (k << 8) | (t & 255))];

    bfly16<0>(r, sc[8], ss[8]);
    bfly16<1>(r, sc[9], ss[9]);
    bfly16<2>(r, sc[10], ss[10]);
    bfly16<3>(r, sc[11], ss[11]);

    __syncthreads();
#pragma unroll
    for (int k = 0; k < 16; k++)
        sm[swz(((t >> 8) << 12) | (k << 8) | (t & 255))] = r[k];
    __syncthreads();

    // regs own bits 10..13 ; butterfly bits 12,13 (k bits 2,3)
#pragma unroll
    for (int k = 0; k < 16; k++)
        r[k] = sm[swz((k << 10) | t)];

    bfly16<2>(r, sc[12], ss[12]);
    bfly16<3>(r, sc[13], ss[13]);

    if (!LAST) {
        // diagonal sign then store (coalesced per-k across the warp)
#pragma unroll
        for (int k = 0; k < 16; k++) {
            int x = base | (k << 10) | t;
            unsigned w = g_sign[x >> 5];
            float v = r[k];
            if ((w >> (x & 31)) & 1) v = -v;
            g_state[x] = v;
        }
    } else {
        // fused expectation values: out[q] = sum probs * (1 - 2*bit_{21-q})
        // sign^2 == 1 so the layer-3 diagonal is skipped entirely.
        float P = 0.f, S0 = 0.f, S1 = 0.f, S2 = 0.f, S3 = 0.f;
#pragma unroll
        for (int k = 0; k < 16; k++) {
            float p = r[k] * r[k];
            P += p;                        // total prob of this thread's elems
            S0 += (k & 1) ? -p : p;        // bit 10
            S1 += (k & 2) ? -p : p;        // bit 11
            S2 += (k & 4) ? -p : p;        // bit 12
            S3 += (k & 8) ? -p : p;        // bit 13
        }
        int lane = t & 31;
        float R0 = (lane & 1)  ? -P : P;   // bit 0
        float R1 = (lane & 2)  ? -P : P;   // bit 1
        float R2 = (lane & 4)  ? -P : P;   // bit 2
        float R3 = (lane & 8)  ? -P : P;   // bit 3
        float R4 = (lane & 16) ? -P : P;   // bit 4
#pragma unroll
        for (int o = 16; o; o >>= 1) {
            P  += __shfl_xor_sync(0xffffffffu, P, o);
            S0 += __shfl_xor_sync(0xffffffffu, S0, o);
            S1 += __shfl_xor_sync(0xffffffffu, S1, o);
            S2 += __shfl_xor_sync(0xffffffffu, S2, o);
            S3 += __shfl_xor_sync(0xffffffffu, S3, o);
            R0 += __shfl_xor_sync(0xffffffffu, R0, o);
            R1 += __shfl_xor_sync(0xffffffffu, R1, o);
            R2 += __shfl_xor_sync(0xffffffffu, R2, o);
            R3 += __shfl_xor_sync(0xffffffffu, R3, o);
            R4 += __shfl_xor_sync(0xffffffffu, R4, o);
        }
        if (lane == 0) {
            int wrp = t >> 5;              // bits 5..9 of the index
            atomicAdd(&acc[0], R0);
            atomicAdd(&acc[1], R1);
            atomicAdd(&acc[2], R2);
            atomicAdd(&acc[3], R3);
            atomicAdd(&acc[4], R4);
#pragma unroll
            for (int b = 5; b < 10; b++)
                atomicAdd(&acc[b], ((wrp >> (b - 5)) & 1) ? -P : P);
            atomicAdd(&acc[10], S0);
            atomicAdd(&acc[11], S1);
            atomicAdd(&acc[12], S2);
            atomicAdd(&acc[13], S3);
#pragma unroll
            for (int b = 14; b < NQ; b++)
                atomicAdd(&acc[b], ((blockIdx.x >> (b - 14)) & 1) ? -P : P);
        }
        __syncthreads();
        if (t < NQ) atomicAdd(&out[NQ - 1 - t], acc[t]);
    }
}

// ---------------------------------------------------------------- launch
extern "C" void kernel_launch(void* const* d_in, const int* in_sizes, int n_in,
                              void* d_out, int out_size) {
    const float* feat = (const float*)d_in[0];
    const float* adj = (const float*)d_in[1];
    const float* params = (const float*)d_in[2];
    float* out = (float*)d_out;

    const int SMEM = LOWDIM * (int)sizeof(float);   // 65536
    cudaFuncSetAttribute(k_passH<1, true>,  cudaFuncAttributeMaxDynamicSharedMemorySize, SMEM);
    cudaFuncSetAttribute(k_passH<2, false>, cudaFuncAttributeMaxDynamicSharedMemorySize, SMEM);
    cudaFuncSetAttribute(k_passH<3, false>, cudaFuncAttributeMaxDynamicSharedMemorySize, SMEM);
    cudaFuncSetAttribute(k_passL<1, false>, cudaFuncAttributeMaxDynamicSharedMemorySize, SMEM);
    cudaFuncSetAttribute(k_passL<2, false>, cudaFuncAttributeMaxDynamicSharedMemorySize, SMEM);
    cudaFuncSetAttribute(k_passL<3, true>,  cudaFuncAttributeMaxDynamicSharedMemorySize, SMEM);

    k_setup<<<1, 128>>>(feat, adj, params, out);
    k_sign<<<DIM / 256, 256>>>();

    k_passH<1, true><<<LOWDIM / 64, 1024, SMEM>>>();
    k_passL<1, false><<<DIM / LOWDIM, 1024, SMEM>>>(out);
    k_passH<2, false><<<LOWDIM / 64, 1024, SMEM>>>();
    k_passL<2, false><<<DIM / LOWDIM, 1024, SMEM>>>(out);
    k_passH<3, false><<<LOWDIM / 64, 1024, SMEM>>>();
    k_passL<3, true><<<DIM / LOWDIM, 1024, SMEM>>>(out);
}

// round 3
// speedup vs baseline: 1.1137x; 1.0595x over previous
#include <cuda_runtime.h>
#include <math.h>

// GraphQNN: 22-qubit real-amplitude state-vector simulation.
// R3: stall-reduction round.
//  - passL uses ONE fixed smem layout w(x) (XOR swizzle, conflict-free for all
//    4 gather views) -> in-place exchanges, 3 barriers instead of 7.
//  - butterfly coefficients via __shfl_sync (lane b holds coef b): no coef
//    smem, no coef barrier.
//  - diagonal sign moved from passL tail to passH load (overlaps state LDG).

#define NQ 22
#define DIM (1 << NQ)
#define LOWB 14
#define LOWDIM (1 << LOWB)

__device__ float g_state[DIM];
__device__ unsigned g_sign[DIM / 32];
__device__ float g_c[4][NQ];   // [stage][bit] stage0 = features, 1..3 = layers
__device__ float g_s[4][NQ];
__device__ unsigned g_mask[NQ];

// ---------------------------------------------------------------- setup
__global__ void k_setup(const float* __restrict__ feat,
                        const float* __restrict__ adj,
                        const float* __restrict__ params,
                        float* __restrict__ out) {
    int t = threadIdx.x;
    if (t < 4 * NQ) {
        int s = t / NQ;
        int b = t % NQ;
        int q = NQ - 1 - b;
        float th = (s == 0 ? feat[q] : params[(s - 1) * NQ + q]) * 0.5f;
        g_c[s][b] = cosf(th);
        g_s[s][b] = sinf(th);
    }
    if (t < NQ) {
        unsigned m = 0;
        for (int j = t + 1; j < NQ; j++)
            if (adj[t * NQ + j] > 0.0f) m |= (1u << (NQ - 1 - j));
        g_mask[t] = m;
        out[t] = 0.0f;
    }
}

// ---------------------------------------------------------------- sign pack
__global__ void k_sign() {
    __shared__ unsigned mk[NQ];
    int t = threadIdx.x;
    if (t < NQ) mk[t] = g_mask[t];
    __syncthreads();
    unsigned x = blockIdx.x * blockDim.x + t;
    unsigned p = 0;
#pragma unroll
    for (int i = 0; i < NQ; i++)
        p ^= ((x >> (NQ - 1 - i)) & 1u) & ((unsigned)__popc(x & mk[i]) & 1u);
    unsigned bal = __ballot_sync(0xffffffffu, p);
    if ((t & 31) == 0) g_sign[x >> 5] = bal;
}

// ---------------------------------------------------------------- butterfly
template <int BIT>
__device__ __forceinline__ void bfly16(float* r, float c, float s) {
#pragma unroll
    for (int k0 = 0; k0 < 16; k0++) {
        if ((k0 & (1 << BIT)) == 0) {
            int k1 = k0 | (1 << BIT);
            float v0 = r[k0], v1 = r[k1];
            r[k0] = fmaf(c, v0, -(s * v1));
            r[k1] = fmaf(s, v0, c * v1);
        }
    }
}

#define CF(b) __shfl_sync(0xffffffffu, myc, (b))
#define SF(b) __shfl_sync(0xffffffffu, mys, (b))

// ---------------------------------------------------------------- pass H
// bits 14..21. Tile = 256 h-values x 64 low-values. 1 barrier.
// Non-INIT stages apply the previous layer's diagonal sign at load.
template <int STAGE, bool INIT>
__global__ void __launch_bounds__(1024, 2) k_passH() {
    extern __shared__ float sm[];   // 16384 floats
    const int t = threadIdx.x;
    const int lane = t & 31;
    float myc = lane < NQ ? g_c[STAGE][lane] : 0.f;
    float mys = lane < NQ ? g_s[STAGE][lane] : 0.f;

    const int tl = t & 63;
    const int th = t >> 6;
    const int low = (blockIdx.x << 6) + tl;
    float r[16];

    if (INIT) {
        float c0 = lane < NQ ? g_c[0][lane] : 0.f;
        float s0 = lane < NQ ? g_s[0][lane] : 0.f;
        float a = 1.0f;
#pragma unroll
        for (int b = 0; b < LOWB; b++) {
            float cb = __shfl_sync(0xffffffffu, c0, b);
            float sb = __shfl_sync(0xffffffffu, s0, b);
            a *= ((low >> b) & 1) ? sb : cb;
        }
#pragma unroll
        for (int b = 0; b < 4; b++) {
            float cb = __shfl_sync(0xffffffffu, c0, LOWB + 4 + b);
            float sb = __shfl_sync(0xffffffffu, s0, LOWB + 4 + b);
            a *= ((th >> b) & 1) ? sb : cb;
        }
        float pc[4], ps[4];
#pragma unroll
        for (int b = 0; b < 4; b++) {
            pc[b] = __shfl_sync(0xffffffffu, c0, LOWB + b);
            ps[b] = __shfl_sync(0xffffffffu, s0, LOWB + b);
        }
#pragma unroll
        for (int k = 0; k < 16; k++) {
            float a2 = a;
#pragma unroll
            for (int b = 0; b < 4; b++)
                a2 *= ((k >> b) & 1) ? ps[b] : pc[b];
            r[k] = a2;
        }
    } else {
        // load + previous layer's diagonal sign (overlapped LDGs)
#pragma unroll
        for (int k = 0; k < 16; k++) {
            float v = g_state[((th * 16 + k) << LOWB) | low];
            unsigned sw = g_sign[((th * 16 + k) << 9) | (low >> 5)];
            if ((sw >> (low & 31)) & 1) v = -v;
            r[k] = v;
        }
    }

    // butterflies on h bits 0..3  (global bits 14..17)
    bfly16<0>(r, CF(LOWB + 0), SF(LOWB + 0));
    bfly16<1>(r, CF(LOWB + 1), SF(LOWB + 1));
    bfly16<2>(r, CF(LOWB + 2), SF(LOWB + 2));
    bfly16<3>(r, CF(LOWB + 3), SF(LOWB + 3));

    // exchange: [h][tl] layout, conflict-free both directions
#pragma unroll
    for (int k = 0; k < 16; k++)
        sm[((th << 4) | k) * 64 + tl] = r[k];
    __syncthreads();
#pragma unroll
    for (int k = 0; k < 16; k++)
        r[k] = sm[((k << 4) | th) * 64 + tl];

    // butterflies on h bits 4..7  (global bits 18..21)
    bfly16<0>(r, CF(LOWB + 4), SF(LOWB + 4));
    bfly16<1>(r, CF(LOWB + 5), SF(LOWB + 5));
    bfly16<2>(r, CF(LOWB + 6), SF(LOWB + 6));
    bfly16<3>(r, CF(LOWB + 7), SF(LOWB + 7));

#pragma unroll
    for (int k = 0; k < 16; k++)
        g_state[(((k << 4) | th) << LOWB) | low] = r[k];
}

// ---------------------------------------------------------------- pass L
// bits 0..13 within a contiguous 16384-element block.
// FIXED smem layout: word address w(x); bank bits
//   b0=x0^x5 b1=x1^x6 b2=x2^x7 b3=x3^x8 b4=x4^x8
// -> conflict-free for all 4 thread views (A write, B/C gather+scatter, D gather).
__device__ __forceinline__ int lw(int x) {
    return x ^ ((x >> 5) & 15) ^ ((x >> 4) & 16);
}

template <int STAGE, bool LAST>
__global__ void __launch_bounds__(1024, 2) k_passL(float* __restrict__ out) {
    extern __shared__ float sm[];   // 16384 floats
    __shared__ float acc[NQ];
    const int t = threadIdx.x;
    const int lane = t & 31;
    const int base = blockIdx.x << LOWB;
    float myc = lane < NQ ? g_c[STAGE][lane] : 0.f;
    float mys = lane < NQ ? g_s[STAGE][lane] : 0.f;
    float r[16];

    if (LAST && t < NQ) acc[t] = 0.0f;

    // ---- A: regs own bits 0..3 (x = t*16+k, contiguous float4 loads)
    const float4* gp = reinterpret_cast<const float4*>(&g_state[base + t * 16]);
    float4 q0 = gp[0], q1 = gp[1], q2 = gp[2], q3 = gp[3];
    r[0] = q0.x;  r[1] = q0.y;  r[2] = q0.z;  r[3] = q0.w;
    r[4] = q1.x;  r[5] = q1.y;  r[6] = q1.z;  r[7] = q1.w;
    r[8] = q2.x;  r[9] = q2.y;  r[10] = q2.z; r[11] = q2.w;
    r[12] = q3.x; r[13] = q3.y; r[14] = q3.z; r[15] = q3.w;

    bfly16<0>(r, CF(0), SF(0));
    bfly16<1>(r, CF(1), SF(1));
    bfly16<2>(r, CF(2), SF(2));
    bfly16<3>(r, CF(3), SF(3));

#pragma unroll
    for (int k = 0; k < 16; k++)
        sm[lw((t << 4) | k)] = r[k];
    __syncthreads();

    // ---- B: regs own bits 4..7 ; fixed x[0..3]=t&15, x[8..13]=t>>4
    {
        const int xb = (t & 15) | ((t >> 4) << 8);
#pragma unroll
        for (int k = 0; k < 16; k++)
            r[k] = sm[lw(xb | (k << 4))];

        bfly16<0>(r, CF(4), SF(4));
        bfly16<1>(r, CF(5), SF(5));
        bfly16<2>(r, CF(6), SF(6));
        bfly16<3>(r, CF(7), SF(7));

#pragma unroll
        for (int k = 0; k < 16; k++)
            sm[lw(xb | (k << 4))] = r[k];
    }
    __syncthreads();

    // ---- C: regs own bits 8..11 ; fixed x[0..7]=t&255, x[12..13]=t>>8
    {
        const int xc = (t & 255) | ((t >> 8) << 12);
#pragma unroll
        for (int k = 0; k < 16; k++)
            r[k] = sm[lw(xc | (k << 8))];

        bfly16<0>(r, CF(8), SF(8));
        bfly16<1>(r, CF(9), SF(9));
        bfly16<2>(r, CF(10), SF(10));
        bfly16<3>(r, CF(11), SF(11));

#pragma unroll
        for (int k = 0; k < 16; k++)
            sm[lw(xc | (k << 8))] = r[k];
    }
    __syncthreads();

    // ---- D: regs own bits 10..13 ; fixed x[0..9]=t ; butterfly bits 12,13
#pragma unroll
    for (int k = 0; k < 16; k++)
        r[k] = sm[lw(t | (k << 10))];

    bfly16<2>(r, CF(12), SF(12));
    bfly16<3>(r, CF(13), SF(13));

    if (!LAST) {
        // plain coalesced stores (sign applied by the next passH at load)
#pragma unroll
        for (int k = 0; k < 16; k++)
            g_state[base | (k << 10) | t] = r[k];
    } else {
        // fused expectation values: out[q] = sum probs * (1 - 2*bit_{21-q})
        // layer-3 sign^2 == 1, skipped.
        float P = 0.f, S0 = 0.f, S1 = 0.f, S2 = 0.f, S3 = 0.f;
#pragma unroll
        for (int k = 0; k < 16; k++) {
            float p = r[k] * r[k];
            P += p;
            S0 += (k & 1) ? -p : p;        // bit 10
            S1 += (k & 2) ? -p : p;        // bit 11
            S2 += (k & 4) ? -p : p;        // bit 12
            S3 += (k & 8) ? -p : p;        // bit 13
        }
        float R0 = (lane & 1)  ? -P : P;   // bit 0
        float R1 = (lane & 2)  ? -P : P;   // bit 1
        float R2 = (lane & 4)  ? -P : P;   // bit 2
        float R3 = (lane & 8)  ? -P : P;   // bit 3
        float R4 = (lane & 16) ? -P : P;   // bit 4
#pragma unroll
        for (int o = 16; o; o >>= 1) {
            P  += __shfl_xor_sync(0xffffffffu, P, o);
            S0 += __shfl_xor_sync(0xffffffffu, S0, o);
            S1 += __shfl_xor_sync(0xffffffffu, S1, o);
            S2 += __shfl_xor_sync(0xffffffffu, S2, o);
            S3 += __shfl_xor_sync(0xffffffffu, S3, o);
            R0 += __shfl_xor_sync(0xffffffffu, R0, o);
            R1 += __shfl_xor_sync(0xffffffffu, R1, o);
            R2 += __shfl_xor_sync(0xffffffffu, R2, o);
            R3 += __shfl_xor_sync(0xffffffffu, R3, o);
            R4 += __shfl_xor_sync(0xffffffffu, R4, o);
        }
        if (lane == 0) {
            int wrp = t >> 5;              // bits 5..9
            atomicAdd(&acc[0], R0);
            atomicAdd(&acc[1], R1);
            atomicAdd(&acc[2], R2);
            atomicAdd(&acc[3], R3);
            atomicAdd(&acc[4], R4);
#pragma unroll
            for (int b = 5; b < 10; b++)
                atomicAdd(&acc[b], ((wrp >> (b - 5)) & 1) ? -P : P);
            atomicAdd(&acc[10], S0);
            atomicAdd(&acc[11], S1);
            atomicAdd(&acc[12], S2);
            atomicAdd(&acc[13], S3);
#pragma unroll
            for (int b = 14; b < NQ; b++)
                atomicAdd(&acc[b], ((blockIdx.x >> (b - 14)) & 1) ? -P : P);
        }
        __syncthreads();
        if (t < NQ) atomicAdd(&out[NQ - 1 - t], acc[t]);
    }
}

// ---------------------------------------------------------------- launch
extern "C" void kernel_launch(void* const* d_in, const int* in_sizes, int n_in,
                              void* d_out, int out_size) {
    const float* feat = (const float*)d_in[0];
    const float* adj = (const float*)d_in[1];
    const float* params = (const float*)d_in[2];
    float* out = (float*)d_out;

    const int SMEM = LOWDIM * (int)sizeof(float);   // 65536
    cudaFuncSetAttribute(k_passH<1, true>,  cudaFuncAttributeMaxDynamicSharedMemorySize, SMEM);
    cudaFuncSetAttribute(k_passH<2, false>, cudaFuncAttributeMaxDynamicSharedMemorySize, SMEM);
    cudaFuncSetAttribute(k_passH<3, false>, cudaFuncAttributeMaxDynamicSharedMemorySize, SMEM);
    cudaFuncSetAttribute(k_passL<1, false>, cudaFuncAttributeMaxDynamicSharedMemorySize, SMEM);
    cudaFuncSetAttribute(k_passL<2, false>, cudaFuncAttributeMaxDynamicSharedMemorySize, SMEM);
    cudaFuncSetAttribute(k_passL<3, true>,  cudaFuncAttributeMaxDynamicSharedMemorySize, SMEM);

    k_setup<<<1, 128>>>(feat, adj, params, out);
    k_sign<<<DIM / 256, 256>>>();

    k_passH<1, true><<<LOWDIM / 64, 1024, SMEM>>>();
    k_passL<1, false><<<DIM / LOWDIM, 1024, SMEM>>>(out);
    k_passH<2, false><<<LOWDIM / 64, 1024, SMEM>>>();
    k_passL<2, false><<<DIM / LOWDIM, 1024, SMEM>>>(out);
    k_passH<3, false><<<LOWDIM / 64, 1024, SMEM>>>();
    k_passL<3, true><<<DIM / LOWDIM, 1024, SMEM>>>(out);
}

// round 4
// speedup vs baseline: 1.4459x; 1.2982x over previous
#include <cuda_runtime.h>
#include <math.h>

// GraphQNN: 22-qubit real-amplitude state-vector simulation.
// R4: - k_sign kernel and g_sign bitmask DELETED: graph-parity sign computed
//       algebraically inside passH's load (B(low) ^ popc(h&cl) ^ A(h), with
//       the k-internal part of A(h) built by one warp ballot).
//     - 512 threads x 32 elems/thread in both passes: passL now 3 register
//       arrangements (bits 0-4 / 5-8 / 9-13), 4 smem ops/elem (was 7),
//       2 barriers (was 3); passH 1 exchange, big LDG MLP.

#define NQ 22
#define DIM (1 << NQ)
#define LOWB 14
#define LOWDIM (1 << LOWB)

__device__ float g_state[DIM];
__device__ float g_c[4][NQ];   // [stage][bitpos] stage0 = features, 1..3 = layers
__device__ float g_s[4][NQ];
__device__ unsigned g_pm[NQ];  // per bit position: mask of paired bit positions

// ---------------------------------------------------------------- setup
__global__ void k_setup(const float* __restrict__ feat,
                        const float* __restrict__ adj,
                        const float* __restrict__ params,
                        float* __restrict__ out) {
    int t = threadIdx.x;
    if (t < 4 * NQ) {
        int s = t / NQ;
        int b = t % NQ;
        int q = NQ - 1 - b;   // bit position b <-> qubit NQ-1-b
        float th = (s == 0 ? feat[q] : params[(s - 1) * NQ + q]) * 0.5f;
        g_c[s][b] = cosf(th);
        g_s[s][b] = sinf(th);
    }
    if (t < NQ) {
        int q = NQ - 1 - t;   // qubit of bit position t
        unsigned m = 0;
        for (int qq = 0; qq < NQ; qq++) {
            if (qq == q) continue;
            int i = q < qq ? q : qq;
            int j = q < qq ? qq : q;
            if (adj[i * NQ + j] > 0.0f) m |= (1u << (NQ - 1 - qq));
        }
        g_pm[t] = m;
        out[t] = 0.0f;
    }
}

// ---------------------------------------------------------------- butterfly
template <int BIT>
__device__ __forceinline__ void bfly32(float* r, float c, float s) {
#pragma unroll
    for (int k0 = 0; k0 < 32; k0++) {
        if ((k0 & (1 << BIT)) == 0) {
            int k1 = k0 | (1 << BIT);
            float v0 = r[k0], v1 = r[k1];
            r[k0] = fmaf(c, v0, -(s * v1));
            r[k1] = fmaf(s, v0, c * v1);
        }
    }
}

#define CF(b) __shfl_sync(0xffffffffu, myc, (b))
#define SF(b) __shfl_sync(0xffffffffu, mys, (b))

// ---------------------------------------------------------------- pass H
// bits 14..21. Tile = 256 h x 64 low. 512 threads x 32 elems.
// View A: tl=t&63, hhi=t>>6 (h bits 5-7); regs own h bits 0-4 (k).
// View B: tl=t&63, hlo=t>>6 (h bits 0-2); regs own h bits 3-7 -> bfly 5-7.
// Non-INIT applies the graph-parity sign (of the previous layer) at load.
template <int STAGE, bool INIT>
__global__ void __launch_bounds__(512, 2) k_passH() {
    extern __shared__ float sm[];   // 16384 floats
    const int t = threadIdx.x;
    const int lane = t & 31;
    float myc = lane < NQ ? g_c[STAGE][lane] : 0.f;
    float mys = lane < NQ ? g_s[STAGE][lane] : 0.f;

    const int tl = t & 63;
    const unsigned hhi = t >> 6;           // h bits 5-7 (global bits 19-21)
    const int low = (blockIdx.x << 6) + tl;
    float r[32];

    if (INIT) {
        float c0 = lane < NQ ? g_c[0][lane] : 0.f;
        float s0 = lane < NQ ? g_s[0][lane] : 0.f;
        float a = 1.0f;
#pragma unroll
        for (int b = 0; b < LOWB; b++) {
            float cb = __shfl_sync(0xffffffffu, c0, b);
            float sb = __shfl_sync(0xffffffffu, s0, b);
            a *= ((low >> b) & 1) ? sb : cb;
        }
#pragma unroll
        for (int b = 0; b < 3; b++) {
            float cb = __shfl_sync(0xffffffffu, c0, 19 + b);
            float sb = __shfl_sync(0xffffffffu, s0, 19 + b);
            a *= ((hhi >> b) & 1) ? sb : cb;
        }
        float pc[5], ps[5];
#pragma unroll
        for (int b = 0; b < 5; b++) {
            pc[b] = __shfl_sync(0xffffffffu, c0, LOWB + b);
            ps[b] = __shfl_sync(0xffffffffu, s0, LOWB + b);
        }
#pragma unroll
        for (int k = 0; k < 32; k++) {
            float a2 = a;
#pragma unroll
            for (int b = 0; b < 5; b++)
                a2 *= ((k >> b) & 1) ? ps[b] : pc[b];
            r[k] = a2;
        }
    } else {
        // ---- inline graph-parity sign for x = (((hhi<<5)|k)<<14)|low ----
        // B(low): pairs within low bits
        unsigned ulow = (unsigned)low;
        unsigned Bb = 0;
#pragma unroll
        for (int a = 1; a < LOWB; a++)
            Bb ^= ((ulow >> a) & 1u) &
                  ((unsigned)__popc(ulow & g_pm[a] & ((1u << a) - 1u)) & 1u);
        // cl: for each high bit j (0..7), parity of its low partners
        unsigned cl = 0;
#pragma unroll
        for (int j = 0; j < 8; j++)
            cl |= ((unsigned)__popc(ulow & g_pm[14 + j] & 0x3FFFu) & 1u) << j;
        // chm: cross k-bits (14-18) with hhi-bits (19-21)
        unsigned chm = 0;
#pragma unroll
        for (int a = 0; a < 5; a++)
            chm |= ((unsigned)__popc(hhi & ((g_pm[14 + a] >> 19) & 7u)) & 1u) << a;
        // A_hh: pairs within hhi bits
        unsigned Ahh = 0;
#pragma unroll
        for (int a = 1; a < 3; a++)
            Ahh ^= ((hhi >> a) & 1u) &
                   ((unsigned)__popc(hhi & ((g_pm[19 + a] >> 19) & ((1u << a) - 1u))) & 1u);
        // akk: per-k internal parity of bits 14-18, one bit per lane via ballot
        unsigned ab = 0;
#pragma unroll
        for (int a = 1; a < 5; a++)
            ab ^= (((unsigned)lane >> a) & 1u) &
                  ((unsigned)__popc((unsigned)lane & ((g_pm[14 + a] >> 14) & ((1u << a) - 1u))) & 1u);
        unsigned akk = __ballot_sync(0xffffffffu, ab);
        unsigned km = (cl & 31u) ^ chm;
        unsigned cbase = Bb ^ ((unsigned)__popc(hhi & (cl >> 5)) & 1u) ^ Ahh;

#pragma unroll
        for (int k = 0; k < 32; k++) {
            float v = g_state[(((hhi << 5) | k) << LOWB) | low];
            unsigned sb = cbase ^ ((akk >> k) & 1u) ^ ((unsigned)__popc(k & km) & 1u);
            r[k] = __int_as_float(__float_as_int(v) ^ (sb << 31));
        }
    }

    // butterflies on h bits 0-4 (global 14-18)
    bfly32<0>(r, CF(LOWB + 0), SF(LOWB + 0));
    bfly32<1>(r, CF(LOWB + 1), SF(LOWB + 1));
    bfly32<2>(r, CF(LOWB + 2), SF(LOWB + 2));
    bfly32<3>(r, CF(LOWB + 3), SF(LOWB + 3));
    bfly32<4>(r, CF(LOWB + 4), SF(LOWB + 4));

    // exchange via smem: addr = (h<<6)|tl  (lanes vary tl -> conflict-free)
#pragma unroll
    for (int k = 0; k < 32; k++)
        sm[((((hhi << 5) | k) << 6)) | tl] = r[k];
    __syncthreads();
    const unsigned hlo = t >> 6;           // h bits 0-2 in view B
#pragma unroll
    for (int k = 0; k < 32; k++)
        r[k] = sm[((((k << 3) | hlo) << 6)) | tl];

    // butterflies on h bits 5-7 (global 19-21) = k bits 2-4
    bfly32<2>(r, CF(19), SF(19));
    bfly32<3>(r, CF(20), SF(20));
    bfly32<4>(r, CF(21), SF(21));

#pragma unroll
    for (int k = 0; k < 32; k++)
        g_state[((((k << 3) | hlo)) << LOWB) | low] = r[k];
}

// ---------------------------------------------------------------- pass L
// bits 0..13 within a contiguous 16384-element block. 512 threads x 32.
// Fixed smem layout w(x) = x ^ ((x>>5)&31); conflict-free for views A,B,C.
__device__ __forceinline__ int lw(int x) { return x ^ ((x >> 5) & 31); }

template <int STAGE, bool LAST>
__global__ void __launch_bounds__(512, 2) k_passL(float* __restrict__ out) {
    extern __shared__ float sm[];   // 16384 floats
    __shared__ float acc[NQ];
    const int t = threadIdx.x;
    const int lane = t & 31;
    const int base = blockIdx.x << LOWB;
    float myc = lane < NQ ? g_c[STAGE][lane] : 0.f;
    float mys = lane < NQ ? g_s[STAGE][lane] : 0.f;
    float r[32];

    if (LAST && t < NQ) acc[t] = 0.0f;

    // ---- A: regs own bits 0-4 (x = t*32+k): contiguous float4 loads
    const float4* gp = reinterpret_cast<const float4*>(&g_state[base + t * 32]);
#pragma unroll
    for (int i = 0; i < 8; i++) {
        float4 q = gp[i];
        r[i * 4 + 0] = q.x; r[i * 4 + 1] = q.y;
        r[i * 4 + 2] = q.z; r[i * 4 + 3] = q.w;
    }

    bfly32<0>(r, CF(0), SF(0));
    bfly32<1>(r, CF(1), SF(1));
    bfly32<2>(r, CF(2), SF(2));
    bfly32<3>(r, CF(3), SF(3));
    bfly32<4>(r, CF(4), SF(4));

#pragma unroll
    for (int k = 0; k < 32; k++)
        sm[lw((t << 5) | k)] = r[k];
    __syncthreads();

    // ---- B: regs own bits 5-9; fixed bits 0-4 = t&31, bits 10-13 = t>>5
    {
        const int xb = (t & 31) | ((t >> 5) << 10);
#pragma unroll
        for (int k = 0; k < 32; k++)
            r[k] = sm[lw(xb | (k << 5))];

        bfly32<0>(r, CF(5), SF(5));
        bfly32<1>(r, CF(6), SF(6));
        bfly32<2>(r, CF(7), SF(7));
        bfly32<3>(r, CF(8), SF(8));

#pragma unroll
        for (int k = 0; k < 32; k++)
            sm[lw(xb | (k << 5))] = r[k];
    }
    __syncthreads();

    // ---- C: regs own bits 9-13; fixed bits 0-8 = t
#pragma unroll
    for (int k = 0; k < 32; k++)
        r[k] = sm[lw(t | (k << 9))];

    bfly32<0>(r, CF(9),  SF(9));
    bfly32<1>(r, CF(10), SF(10));
    bfly32<2>(r, CF(11), SF(11));
    bfly32<3>(r, CF(12), SF(12));
    bfly32<4>(r, CF(13), SF(13));

    if (!LAST) {
        // coalesced stores (sign applied by the next passH at load)
#pragma unroll
        for (int k = 0; k < 32; k++)
            g_state[base | (k << 9) | t] = r[k];
    } else {
        // fused expectation values (layer-3 sign^2 == 1, skipped).
        // x bits: 0-4 lane, 5-8 warp id, 9-13 k, 14-21 block.
        float P = 0.f, S0 = 0.f, S1 = 0.f, S2 = 0.f, S3 = 0.f, S4 = 0.f;
#pragma unroll
        for (int k = 0; k < 32; k++) {
            float p = r[k] * r[k];
            P += p;
            S0 += (k & 1)  ? -p : p;   // bit 9
            S1 += (k & 2)  ? -p : p;   // bit 10
            S2 += (k & 4)  ? -p : p;   // bit 11
            S3 += (k & 8)  ? -p : p;   // bit 12
            S4 += (k & 16) ? -p : p;   // bit 13
        }
        float R0 = (lane & 1)  ? -P : P;   // bit 0
        float R1 = (lane & 2)  ? -P : P;   // bit 1
        float R2 = (lane & 4)  ? -P : P;   // bit 2
        float R3 = (lane & 8)  ? -P : P;   // bit 3
        float R4 = (lane & 16) ? -P : P;   // bit 4
#pragma unroll
        for (int o = 16; o; o >>= 1) {
            P  += __shfl_xor_sync(0xffffffffu, P, o);
            S0 += __shfl_xor_sync(0xffffffffu, S0, o);
            S1 += __shfl_xor_sync(0xffffffffu, S1, o);
            S2 += __shfl_xor_sync(0xffffffffu, S2, o);
            S3 += __shfl_xor_sync(0xffffffffu, S3, o);
            S4 += __shfl_xor_sync(0xffffffffu, S4, o);
            R0 += __shfl_xor_sync(0xffffffffu, R0, o);
            R1 += __shfl_xor_sync(0xffffffffu, R1, o);
            R2 += __shfl_xor_sync(0xffffffffu, R2, o);
            R3 += __shfl_xor_sync(0xffffffffu, R3, o);
            R4 += __shfl_xor_sync(0xffffffffu, R4, o);
        }
        if (lane == 0) {
            int wrp = t >> 5;              // bits 5-8
            atomicAdd(&acc[0], R0);
            atomicAdd(&acc[1], R1);
            atomicAdd(&acc[2], R2);
            atomicAdd(&acc[3], R3);
            atomicAdd(&acc[4], R4);
#pragma unroll
            for (int b = 5; b < 9; b++)
                atomicAdd(&acc[b], ((wrp >> (b - 5)) & 1) ? -P : P);
            atomicAdd(&acc[9],  S0);
            atomicAdd(&acc[10], S1);
            atomicAdd(&acc[11], S2);
            atomicAdd(&acc[12], S3);
            atomicAdd(&acc[13], S4);
#pragma unroll
            for (int b = 14; b < NQ; b++)
                atomicAdd(&acc[b], ((blockIdx.x >> (b - 14)) & 1) ? -P : P);
        }
        __syncthreads();
        if (t < NQ) atomicAdd(&out[NQ - 1 - t], acc[t]);
    }
}

// ---------------------------------------------------------------- launch
extern "C" void kernel_launch(void* const* d_in, const int* in_sizes, int n_in,
                              void* d_out, int out_size) {
    const float* feat = (const float*)d_in[0];
    const float* adj = (const float*)d_in[1];
    const float* params = (const float*)d_in[2];
    float* out = (float*)d_out;

    const int SMEM = LOWDIM * (int)sizeof(float);   // 65536
    cudaFuncSetAttribute(k_passH<1, true>,  cudaFuncAttributeMaxDynamicSharedMemorySize, SMEM);
    cudaFuncSetAttribute(k_passH<2, false>, cudaFuncAttributeMaxDynamicSharedMemorySize, SMEM);
    cudaFuncSetAttribute(k_passH<3, false>, cudaFuncAttributeMaxDynamicSharedMemorySize, SMEM);
    cudaFuncSetAttribute(k_passL<1, false>, cudaFuncAttributeMaxDynamicSharedMemorySize, SMEM);
    cudaFuncSetAttribute(k_passL<2, false>, cudaFuncAttributeMaxDynamicSharedMemorySize, SMEM);
    cudaFuncSetAttribute(k_passL<3, true>,  cudaFuncAttributeMaxDynamicSharedMemorySize, SMEM);

    k_setup<<<1, 128>>>(feat, adj, params, out);

    k_passH<1, true><<<LOWDIM / 64, 512, SMEM>>>();
    k_passL<1, false><<<DIM / LOWDIM, 512, SMEM>>>(out);
    k_passH<2, false><<<LOWDIM / 64, 512, SMEM>>>();
    k_passL<2, false><<<DIM / LOWDIM, 512, SMEM>>>(out);
    k_passH<3, false><<<LOWDIM / 64, 512, SMEM>>>();
    k_passL<3, true><<<DIM / LOWDIM, 512, SMEM>>>(out);
}

// round 5
// speedup vs baseline: 1.4483x; 1.0017x over previous
#include <cuda_runtime.h>
#include <math.h>

// GraphQNN: 22-qubit real-amplitude state-vector simulation.
// R5: 5 sweeps instead of 6. The diagonal sign is layer-independent and
// computable in either access view, so adjacent layers' hi-bit RY stages fuse
// into one column sweep:
//   K1 passL : init product state (analytic, no load) + stage1 low RYs
//   K2 passHH: stage1 hi RYs -> sign -> stage2 hi RYs   (2 barriers)
//   K3 passL : stage2 low RYs
//   K4 passH1: sign at load -> stage3 hi RYs            (1 barrier)
//   K5 passL : stage3 low RYs + fused expvals (no store; sign3^2==1 skipped)

#define NQ 22
#define DIM (1 << NQ)
#define LOWB 14
#define LOWDIM (1 << LOWB)
#define FULL 0xffffffffu

__device__ float g_state[DIM];
__device__ float g_c[4][NQ];   // [stage][bitpos] stage0 = features, 1..3 = layers
__device__ float g_s[4][NQ];
__device__ unsigned g_pm[NQ];  // per bit position: mask of paired bit positions

__device__ __forceinline__ unsigned par(unsigned v) {
    return (unsigned)__popc(v) & 1u;
}

// ---------------------------------------------------------------- setup
__global__ void k_setup(const float* __restrict__ feat,
                        const float* __restrict__ adj,
                        const float* __restrict__ params,
                        float* __restrict__ out) {
    int t = threadIdx.x;
    if (t < 4 * NQ) {
        int s = t / NQ;
        int b = t % NQ;
        int q = NQ - 1 - b;   // bit position b <-> qubit NQ-1-b
        float th = (s == 0 ? feat[q] : params[(s - 1) * NQ + q]) * 0.5f;
        g_c[s][b] = cosf(th);
        g_s[s][b] = sinf(th);
    }
    if (t < NQ) {
        int q = NQ - 1 - t;
        unsigned m = 0;
        for (int qq = 0; qq < NQ; qq++) {
            if (qq == q) continue;
            int i = q < qq ? q : qq;
            int j = q < qq ? qq : q;
            if (adj[i * NQ + j] > 0.0f) m |= (1u << (NQ - 1 - qq));
        }
        g_pm[t] = m;
        out[t] = 0.0f;
    }
}

// ---------------------------------------------------------------- butterfly
template <int BIT>
__device__ __forceinline__ void bfly32(float* r, float c, float s) {
#pragma unroll
    for (int k0 = 0; k0 < 32; k0++) {
        if ((k0 & (1 << BIT)) == 0) {
            int k1 = k0 | (1 << BIT);
            float v0 = r[k0], v1 = r[k1];
            r[k0] = fmaf(c, v0, -(s * v1));
            r[k1] = fmaf(s, v0, c * v1);
        }
    }
}

// B(low): internal parity pairs among low bits 0..13
__device__ __forceinline__ unsigned signB(unsigned ulow) {
    unsigned Bb = 0;
#pragma unroll
    for (int a = 1; a < LOWB; a++)
        Bb ^= ((ulow >> a) & 1u) & par(ulow & g_pm[a] & ((1u << a) - 1u));
    return Bb;
}
// cl: bit j (j=0..7) = parity of low partners of high bit position 14+j
__device__ __forceinline__ unsigned signCL(unsigned ulow) {
    unsigned cl = 0;
#pragma unroll
    for (int j = 0; j < 8; j++)
        cl |= par(ulow & g_pm[14 + j] & 0x3FFFu) << j;
    return cl;
}

// ---------------------------------------------------------------- K2 passHH
// bits 14..21, two layers fused. Tile 256 h x 64 low. 512 thr x 32.
// View A: t=(hhi<<6)|tl, regs k = h bits 0-4 (global 14-18), hhi = h bits 5-7.
// View B: t=(hlo<<6)|tl, regs k = h bits 3-7 (global 17-21), hlo = h bits 0-2.
template <int S1, int S2>
__global__ void __launch_bounds__(512, 2) k_passHH() {
    extern __shared__ float sm[];   // 16384 floats
    const int t = threadIdx.x;
    const int lane = t & 31;
    float c1 = lane < NQ ? g_c[S1][lane] : 0.f;
    float s1 = lane < NQ ? g_s[S1][lane] : 0.f;
    float c2 = lane < NQ ? g_c[S2][lane] : 0.f;
    float s2 = lane < NQ ? g_s[S2][lane] : 0.f;
#define CF1(b) __shfl_sync(FULL, c1, (b))
#define SF1(b) __shfl_sync(FULL, s1, (b))
#define CF2(b) __shfl_sync(FULL, c2, (b))
#define SF2(b) __shfl_sync(FULL, s2, (b))

    const int tl = t & 63;
    const unsigned hv = t >> 6;          // hhi in view A, hlo in view B
    const int low = (blockIdx.x << 6) + tl;
    const unsigned ulow = (unsigned)low;

    // ---- sign constants for VIEW B: h = (k<<3)|hlo, k bits = global 17-21
    unsigned Bb = signB(ulow);
    unsigned cl = signCL(ulow);
    unsigned Alo = 0;
#pragma unroll
    for (int a = 1; a < 3; a++)
        Alo ^= ((hv >> a) & 1u) & par(hv & ((g_pm[14 + a] >> 14) & ((1u << a) - 1u)));
    unsigned cm = 0;
#pragma unroll
    for (int i = 0; i < 5; i++)
        cm |= par(hv & ((g_pm[17 + i] >> 14) & 7u)) << i;
    const unsigned km = ((cl >> 3) & 31u) ^ cm;
    const unsigned cbase = Bb ^ par(hv & (cl & 7u)) ^ Alo;
    unsigned ab = 0;
#pragma unroll
    for (int i = 1; i < 5; i++)
        ab ^= (((unsigned)lane >> i) & 1u) &
              par((unsigned)lane & ((g_pm[17 + i] >> 17) & ((1u << i) - 1u)));
    const unsigned akk = __ballot_sync(FULL, ab);

    float r[32];
    // ---- view A load (natural layout)
#pragma unroll
    for (int k = 0; k < 32; k++)
        r[k] = g_state[(((hv << 5) | k) << LOWB) | low];

    // stage S1 global bits 14-18 (view A k bits 0-4)
    bfly32<0>(r, CF1(14), SF1(14));
    bfly32<1>(r, CF1(15), SF1(15));
    bfly32<2>(r, CF1(16), SF1(16));
    bfly32<3>(r, CF1(17), SF1(17));
    bfly32<4>(r, CF1(18), SF1(18));

    // exchange A -> B
#pragma unroll
    for (int k = 0; k < 32; k++)
        sm[(((hv << 5) | k) << 6) | tl] = r[k];
    __syncthreads();
#pragma unroll
    for (int k = 0; k < 32; k++)
        r[k] = sm[((((k << 3) | hv) << 6)) | tl];

    // stage S1 global bits 19-21 (view B k bits 2-4)
    bfly32<2>(r, CF1(19), SF1(19));
    bfly32<3>(r, CF1(20), SF1(20));
    bfly32<4>(r, CF1(21), SF1(21));

    // ---- diagonal sign (layer-independent mask)
#pragma unroll
    for (int k = 0; k < 32; k++) {
        unsigned sb = cbase ^ ((akk >> k) & 1u) ^ par((unsigned)k & km);
        r[k] = __int_as_float(__float_as_int(r[k]) ^ (sb << 31));
    }

    // stage S2 global bits 19-21
    bfly32<2>(r, CF2(19), SF2(19));
    bfly32<3>(r, CF2(20), SF2(20));
    bfly32<4>(r, CF2(21), SF2(21));

    // exchange B -> A (per-thread write set == read set: no pre-barrier)
#pragma unroll
    for (int k = 0; k < 32; k++)
        sm[((((k << 3) | hv) << 6)) | tl] = r[k];
    __syncthreads();
#pragma unroll
    for (int k = 0; k < 32; k++)
        r[k] = sm[(((hv << 5) | k) << 6) | tl];

    // stage S2 global bits 14-18
    bfly32<0>(r, CF2(14), SF2(14));
    bfly32<1>(r, CF2(15), SF2(15));
    bfly32<2>(r, CF2(16), SF2(16));
    bfly32<3>(r, CF2(17), SF2(17));
    bfly32<4>(r, CF2(18), SF2(18));

#pragma unroll
    for (int k = 0; k < 32; k++)
        g_state[(((hv << 5) | k) << LOWB) | low] = r[k];
#undef CF1
#undef SF1
#undef CF2
#undef SF2
}

// ---------------------------------------------------------------- K4 passH1
// sign at load (view A: h = (hhi<<5)|k, k bits = global 14-18) + stage S hi RYs.
template <int S>
__global__ void __launch_bounds__(512, 2) k_passH1() {
    extern __shared__ float sm[];
    const int t = threadIdx.x;
    const int lane = t & 31;
    float myc = lane < NQ ? g_c[S][lane] : 0.f;
    float mys = lane < NQ ? g_s[S][lane] : 0.f;
#define CF(b) __shfl_sync(FULL, myc, (b))
#define SF(b) __shfl_sync(FULL, mys, (b))

    const int tl = t & 63;
    const unsigned hv = t >> 6;          // hhi (h bits 5-7)
    const int low = (blockIdx.x << 6) + tl;
    const unsigned ulow = (unsigned)low;

    float r[32];
    // state LDGs first (maximize MLP overlap with pm loads below)
#pragma unroll
    for (int k = 0; k < 32; k++)
        r[k] = g_state[(((hv << 5) | k) << LOWB) | low];

    // ---- sign constants for VIEW A: h = (hhi<<5)|k, k bits = global 14-18
    unsigned Bb = signB(ulow);
    unsigned cl = signCL(ulow);
    unsigned chm = 0;
#pragma unroll
    for (int a = 0; a < 5; a++)
        chm |= par(hv & ((g_pm[14 + a] >> 19) & 7u)) << a;
    unsigned Ahh = 0;
#pragma unroll
    for (int a = 1; a < 3; a++)
        Ahh ^= ((hv >> a) & 1u) & par(hv & ((g_pm[19 + a] >> 19) & ((1u << a) - 1u)));
    unsigned ab = 0;
#pragma unroll
    for (int a = 1; a < 5; a++)
        ab ^= (((unsigned)lane >> a) & 1u) &
              par((unsigned)lane & ((g_pm[14 + a] >> 14) & ((1u << a) - 1u)));
    const unsigned akk = __ballot_sync(FULL, ab);
    const unsigned km = (cl & 31u) ^ chm;
    const unsigned cbase = Bb ^ par(hv & (cl >> 5)) ^ Ahh;

#pragma unroll
    for (int k = 0; k < 32; k++) {
        unsigned sb = cbase ^ ((akk >> k) & 1u) ^ par((unsigned)k & km);
        r[k] = __int_as_float(__float_as_int(r[k]) ^ (sb << 31));
    }

    // stage S global bits 14-18
    bfly32<0>(r, CF(14), SF(14));
    bfly32<1>(r, CF(15), SF(15));
    bfly32<2>(r, CF(16), SF(16));
    bfly32<3>(r, CF(17), SF(17));
    bfly32<4>(r, CF(18), SF(18));

    // exchange A -> B
#pragma unroll
    for (int k = 0; k < 32; k++)
        sm[(((hv << 5) | k) << 6) | tl] = r[k];
    __syncthreads();
#pragma unroll
    for (int k = 0; k < 32; k++)
        r[k] = sm[((((k << 3) | hv) << 6)) | tl];

    // stage S global bits 19-21
    bfly32<2>(r, CF(19), SF(19));
    bfly32<3>(r, CF(20), SF(20));
    bfly32<4>(r, CF(21), SF(21));

    // store (natural layout, coalesced: lanes vary tl)
#pragma unroll
    for (int k = 0; k < 32; k++)
        g_state[((((k << 3) | hv)) << LOWB) | low] = r[k];
#undef CF
#undef SF
}

// ---------------------------------------------------------------- pass L
// bits 0..13 within a contiguous 16384 block. Fixed smem swizzle.
__device__ __forceinline__ int lw(int x) { return x ^ ((x >> 5) & 31); }

template <int STAGE, bool INIT, bool LAST>
__global__ void __launch_bounds__(512, 2) k_passL(float* __restrict__ out) {
    extern __shared__ float sm[];
    __shared__ float acc[NQ];
    const int t = threadIdx.x;
    const int lane = t & 31;
    const int base = blockIdx.x << LOWB;
    float myc = lane < NQ ? g_c[STAGE][lane] : 0.f;
    float mys = lane < NQ ? g_s[STAGE][lane] : 0.f;
#define CF(b) __shfl_sync(FULL, myc, (b))
#define SF(b) __shfl_sync(FULL, mys, (b))
    float r[32];

    if (LAST && t < NQ) acc[t] = 0.0f;

    if (INIT) {
        // product state of stage-0 RYs: amp(x) = prod_b (x_b ? s0[b] : c0[b])
        float c0 = lane < NQ ? g_c[0][lane] : 0.f;
        float s0 = lane < NQ ? g_s[0][lane] : 0.f;
        float a = 1.0f;
        const unsigned blk = blockIdx.x;     // bits 14-21
#pragma unroll
        for (int b = 0; b < 8; b++) {
            float cb = __shfl_sync(FULL, c0, 14 + b);
            float sb = __shfl_sync(FULL, s0, 14 + b);
            a *= ((blk >> b) & 1) ? sb : cb;
        }
#pragma unroll
        for (int b = 0; b < 9; b++) {        // bits 5-13 = t
            float cb = __shfl_sync(FULL, c0, 5 + b);
            float sb = __shfl_sync(FULL, s0, 5 + b);
            a *= ((t >> b) & 1) ? sb : cb;
        }
        float pc[5], ps[5];
#pragma unroll
        for (int b = 0; b < 5; b++) {
            pc[b] = __shfl_sync(FULL, c0, b);
            ps[b] = __shfl_sync(FULL, s0, b);
        }
#pragma unroll
        for (int k = 0; k < 32; k++) {
            float a2 = a;
#pragma unroll
            for (int b = 0; b < 5; b++)
                a2 *= ((k >> b) & 1) ? ps[b] : pc[b];
            r[k] = a2;
        }
    } else {
        const float4* gp = reinterpret_cast<const float4*>(&g_state[base + t * 32]);
#pragma unroll
        for (int i = 0; i < 8; i++) {
            float4 q = gp[i];
            r[i * 4 + 0] = q.x; r[i * 4 + 1] = q.y;
            r[i * 4 + 2] = q.z; r[i * 4 + 3] = q.w;
        }
    }

    // ---- A: regs own bits 0-4
    bfly32<0>(r, CF(0), SF(0));
    bfly32<1>(r, CF(1), SF(1));
    bfly32<2>(r, CF(2), SF(2));
    bfly32<3>(r, CF(3), SF(3));
    bfly32<4>(r, CF(4), SF(4));

#pragma unroll
    for (int k = 0; k < 32; k++)
        sm[lw((t << 5) | k)] = r[k];
    __syncthreads();

    // ---- B: regs own bits 5-9
    {
        const int xb = (t & 31) | ((t >> 5) << 10);
#pragma unroll
        for (int k = 0; k < 32; k++)
            r[k] = sm[lw(xb | (k << 5))];

        bfly32<0>(r, CF(5), SF(5));
        bfly32<1>(r, CF(6), SF(6));
        bfly32<2>(r, CF(7), SF(7));
        bfly32<3>(r, CF(8), SF(8));

#pragma unroll
        for (int k = 0; k < 32; k++)
            sm[lw(xb | (k << 5))] = r[k];
    }
    __syncthreads();

    // ---- C: regs own bits 9-13
#pragma unroll
    for (int k = 0; k < 32; k++)
        r[k] = sm[lw(t | (k << 9))];

    bfly32<0>(r, CF(9),  SF(9));
    bfly32<1>(r, CF(10), SF(10));
    bfly32<2>(r, CF(11), SF(11));
    bfly32<3>(r, CF(12), SF(12));
    bfly32<4>(r, CF(13), SF(13));

    if (!LAST) {
#pragma unroll
        for (int k = 0; k < 32; k++)
            g_state[base | (k << 9) | t] = r[k];
    } else {
        // fused expectation values. x bits: 0-4 lane, 5-8 warp, 9-13 k, 14-21 blk.
        float P = 0.f, S0 = 0.f, S1 = 0.f, S2 = 0.f, S3 = 0.f, S4 = 0.f;
#pragma unroll
        for (int k = 0; k < 32; k++) {
            float p = r[k] * r[k];
            P += p;
            S0 += (k & 1)  ? -p : p;
            S1 += (k & 2)  ? -p : p;
            S2 += (k & 4)  ? -p : p;
            S3 += (k & 8)  ? -p : p;
            S4 += (k & 16) ? -p : p;
        }
        float R0 = (lane & 1)  ? -P : P;
        float R1 = (lane & 2)  ? -P : P;
        float R2 = (lane & 4)  ? -P : P;
        float R3 = (lane & 8)  ? -P : P;
        float R4 = (lane & 16) ? -P : P;
#pragma unroll
        for (int o = 16; o; o >>= 1) {
            P  += __shfl_xor_sync(FULL, P, o);
            S0 += __shfl_xor_sync(FULL, S0, o);
            S1 += __shfl_xor_sync(FULL, S1, o);
            S2 += __shfl_xor_sync(FULL, S2, o);
            S3 += __shfl_xor_sync(FULL, S3, o);
            S4 += __shfl_xor_sync(FULL, S4, o);
            R0 += __shfl_xor_sync(FULL, R0, o);
            R1 += __shfl_xor_sync(FULL, R1, o);
            R2 += __shfl_xor_sync(FULL, R2, o);
            R3 += __shfl_xor_sync(FULL, R3, o);
            R4 += __shfl_xor_sync(FULL, R4, o);
        }
        if (lane == 0) {
            int wrp = t >> 5;
            atomicAdd(&acc[0], R0);
            atomicAdd(&acc[1], R1);
            atomicAdd(&acc[2], R2);
            atomicAdd(&acc[3], R3);
            atomicAdd(&acc[4], R4);
#pragma unroll
            for (int b = 5; b < 9; b++)
                atomicAdd(&acc[b], ((wrp >> (b - 5)) & 1) ? -P : P);
            atomicAdd(&acc[9],  S0);
            atomicAdd(&acc[10], S1);
            atomicAdd(&acc[11], S2);
            atomicAdd(&acc[12], S3);
            atomicAdd(&acc[13], S4);
#pragma unroll
            for (int b = 14; b < NQ; b++)
                atomicAdd(&acc[b], ((blockIdx.x >> (b - 14)) & 1) ? -P : P);
        }
        __syncthreads();
        if (t < NQ) atomicAdd(&out[NQ - 1 - t], acc[t]);
    }
#undef CF
#undef SF
}

// ---------------------------------------------------------------- launch
extern "C" void kernel_launch(void* const* d_in, const int* in_sizes, int n_in,
                              void* d_out, int out_size) {
    const float* feat = (const float*)d_in[0];
    const float* adj = (const float*)d_in[1];
    const float* params = (const float*)d_in[2];
    float* out = (float*)d_out;

    const int SMEM = LOWDIM * (int)sizeof(float);   // 65536
    cudaFuncSetAttribute(k_passL<1, true,  false>, cudaFuncAttributeMaxDynamicSharedMemorySize, SMEM);
    cudaFuncSetAttribute(k_passHH<1, 2>,           cudaFuncAttributeMaxDynamicSharedMemorySize, SMEM);
    cudaFuncSetAttribute(k_passL<2, false, false>, cudaFuncAttributeMaxDynamicSharedMemorySize, SMEM);
    cudaFuncSetAttribute(k_passH1<3>,              cudaFuncAttributeMaxDynamicSharedMemorySize, SMEM);
    cudaFuncSetAttribute(k_passL<3, false, true>,  cudaFuncAttributeMaxDynamicSharedMemorySize, SMEM);

    k_setup<<<1, 128>>>(feat, adj, params, out);

    k_passL<1, true,  false><<<DIM / LOWDIM, 512, SMEM>>>(out);
    k_passHH<1, 2>          <<<LOWDIM / 64, 512, SMEM>>>();
    k_passL<2, false, false><<<DIM / LOWDIM, 512, SMEM>>>(out);
    k_passH1<3>             <<<LOWDIM / 64, 512, SMEM>>>();
    k_passL<3, false, true> <<<DIM / LOWDIM, 512, SMEM>>>(out);
}

// round 6
// speedup vs baseline: 1.7244x; 1.1906x over previous
#include <cuda_runtime.h>
#include <math.h>

// GraphQNN: 22-qubit real-amplitude state-vector simulation.
// R6: packed f32x2 butterflies (PTX fma.rn.f32x2 / mul.rn.f32x2 -> FFMA2).
// State held as 16 register pairs; pair-internal bit scalar, other bits packed
// -> ~40% fewer FMA-pipe instructions. View-A smem stores are STS.64 with a
// pair-preserving swizzle x ^ (((x>>5)&15)<<1) (conflict-free in all views).
// Sweep structure unchanged from R5 (5 sweeps):
//   K1 passL : init product state + stage1 low RYs
//   K2 passHH: stage1 hi RYs -> sign -> stage2 hi RYs
//   K3 passL : stage2 low RYs
//   K4 passH1: sign at load -> stage3 hi RYs
//   K5 passL : stage3 low RYs + fused expvals

#define NQ 22
#define DIM (1 << NQ)
#define LOWB 14
#define LOWDIM (1 << LOWB)
#define FULL 0xffffffffu
typedef unsigned long long ull;

__device__ float g_state[DIM];
__device__ float g_c[4][NQ];   // [stage][bitpos] stage0 = features, 1..3 = layers
__device__ float g_s[4][NQ];
__device__ unsigned g_pm[NQ];  // per bit position: mask of paired bit positions

__device__ __forceinline__ unsigned par(unsigned v) {
    return (unsigned)__popc(v) & 1u;
}

// ---------------------------------------------------------------- f32x2
__device__ __forceinline__ ull pk2(float x, float y) {
    ull r; asm("mov.b64 %0, {%1,%2};" : "=l"(r) : "f"(x), "f"(y)); return r;
}
__device__ __forceinline__ float2 upk2(ull v) {
    float2 f; asm("mov.b64 {%0,%1}, %2;" : "=f"(f.x), "=f"(f.y) : "l"(v)); return f;
}
__device__ __forceinline__ ull mul2_(ull a, ull b) {
    ull r; asm("mul.rn.f32x2 %0, %1, %2;" : "=l"(r) : "l"(a), "l"(b)); return r;
}
__device__ __forceinline__ ull fma2_(ull a, ull b, ull c) {
    ull r; asm("fma.rn.f32x2 %0, %1, %2, %3;" : "=l"(r) : "l"(a), "l"(b), "l"(c)); return r;
}

// butterfly on 32 elements held as 16 pairs p[i] = (elem 2i, elem 2i+1).
// BIT = view-local bit index (0 = pair-internal, scalar; >=1 packed).
template <int BIT>
__device__ __forceinline__ void bflyp(ull* p, float c, float s) {
    if (BIT == 0) {
#pragma unroll
        for (int i = 0; i < 16; i++) {
            float2 v = upk2(p[i]);
            p[i] = pk2(fmaf(c, v.x, -(s * v.y)), fmaf(s, v.x, c * v.y));
        }
    } else {
        const ull cc = pk2(c, c), ss = pk2(s, s), ns = pk2(-s, -s);
#pragma unroll
        for (int i0 = 0; i0 < 16; i0++) {
            if ((i0 & (1 << (BIT - 1))) == 0) {
                int i1 = i0 | (1 << (BIT - 1));
                ull v0 = p[i0], v1 = p[i1];
                p[i0] = fma2_(cc, v0, mul2_(ns, v1));
                p[i1] = fma2_(ss, v0, mul2_(cc, v1));
            }
        }
    }
}

// ---------------------------------------------------------------- setup
__global__ void k_setup(const float* __restrict__ feat,
                        const float* __restrict__ adj,
                        const float* __restrict__ params,
                        float* __restrict__ out) {
    int t = threadIdx.x;
    if (t < 4 * NQ) {
        int s = t / NQ;
        int b = t % NQ;
        int q = NQ - 1 - b;   // bit position b <-> qubit NQ-1-b
        float th = (s == 0 ? feat[q] : params[(s - 1) * NQ + q]) * 0.5f;
        g_c[s][b] = cosf(th);
        g_s[s][b] = sinf(th);
    }
    if (t < NQ) {
        int q = NQ - 1 - t;
        unsigned m = 0;
        for (int qq = 0; qq < NQ; qq++) {
            if (qq == q) continue;
            int i = q < qq ? q : qq;
            int j = q < qq ? qq : q;
            if (adj[i * NQ + j] > 0.0f) m |= (1u << (NQ - 1 - qq));
        }
        g_pm[t] = m;
        out[t] = 0.0f;
    }
}

// B(low): internal parity pairs among low bits 0..13
__device__ __forceinline__ unsigned signB(unsigned ulow) {
    unsigned Bb = 0;
#pragma unroll
    for (int a = 1; a < LOWB; a++)
        Bb ^= ((ulow >> a) & 1u) & par(ulow & g_pm[a] & ((1u << a) - 1u));
    return Bb;
}
// cl: bit j (j=0..7) = parity of low partners of high bit position 14+j
__device__ __forceinline__ unsigned signCL(unsigned ulow) {
    unsigned cl = 0;
#pragma unroll
    for (int j = 0; j < 8; j++)
        cl |= par(ulow & g_pm[14 + j] & 0x3FFFu) << j;
    return cl;
}

// ---------------------------------------------------------------- K2 passHH
// bits 14..21, two layers fused. Tile 256 h x 64 low. 512 thr x 32.
// View A: regs k = h bits 0-4 (global 14-18), hv = h bits 5-7.
// View B: regs k = h bits 3-7 (global 17-21), hv = h bits 0-2.
template <int S1, int S2>
__global__ void __launch_bounds__(512, 2) k_passHH() {
    extern __shared__ float sm[];   // 16384 floats
    const int t = threadIdx.x;
    const int lane = t & 31;
    float c1 = lane < NQ ? g_c[S1][lane] : 0.f;
    float s1 = lane < NQ ? g_s[S1][lane] : 0.f;
    float c2 = lane < NQ ? g_c[S2][lane] : 0.f;
    float s2 = lane < NQ ? g_s[S2][lane] : 0.f;
#define CF1(b) __shfl_sync(FULL, c1, (b))
#define SF1(b) __shfl_sync(FULL, s1, (b))
#define CF2(b) __shfl_sync(FULL, c2, (b))
#define SF2(b) __shfl_sync(FULL, s2, (b))

    const int tl = t & 63;
    const unsigned hv = t >> 6;          // hhi in view A, hlo in view B
    const int low = (blockIdx.x << 6) + tl;
    const unsigned ulow = (unsigned)low;

    // ---- sign constants for VIEW B: h = (k<<3)|hlo, k bits = global 17-21
    unsigned Bb = signB(ulow);
    unsigned cl = signCL(ulow);
    unsigned Alo = 0;
#pragma unroll
    for (int a = 1; a < 3; a++)
        Alo ^= ((hv >> a) & 1u) & par(hv & ((g_pm[14 + a] >> 14) & ((1u << a) - 1u)));
    unsigned cm = 0;
#pragma unroll
    for (int i = 0; i < 5; i++)
        cm |= par(hv & ((g_pm[17 + i] >> 14) & 7u)) << i;
    const unsigned km = ((cl >> 3) & 31u) ^ cm;
    const unsigned cbase = Bb ^ par(hv & (cl & 7u)) ^ Alo;
    unsigned ab = 0;
#pragma unroll
    for (int i = 1; i < 5; i++)
        ab ^= (((unsigned)lane >> i) & 1u) &
              par((unsigned)lane & ((g_pm[17 + i] >> 17) & ((1u << i) - 1u)));
    const unsigned akk = __ballot_sync(FULL, ab);

    ull p[16];
    // ---- view A load (natural layout), pack pairs
#pragma unroll
    for (int i = 0; i < 16; i++) {
        float lo = g_state[(((hv << 5) | (2 * i)) << LOWB) | low];
        float hi = g_state[(((hv << 5) | (2 * i + 1)) << LOWB) | low];
        p[i] = pk2(lo, hi);
    }

    // stage S1 global bits 14-18 (view A k bits 0-4)
    bflyp<0>(p, CF1(14), SF1(14));
    bflyp<1>(p, CF1(15), SF1(15));
    bflyp<2>(p, CF1(16), SF1(16));
    bflyp<3>(p, CF1(17), SF1(17));
    bflyp<4>(p, CF1(18), SF1(18));

    // exchange A -> B
#pragma unroll
    for (int i = 0; i < 16; i++) {
        float2 v = upk2(p[i]);
        sm[(((hv << 5) | (2 * i)) << 6) | tl] = v.x;
        sm[(((hv << 5) | (2 * i + 1)) << 6) | tl] = v.y;
    }
    __syncthreads();
#pragma unroll
    for (int i = 0; i < 16; i++)
        p[i] = pk2(sm[((((2 * i) << 3) | hv) << 6) | tl],
                   sm[((((2 * i + 1) << 3) | hv) << 6) | tl]);

    // stage S1 global bits 19-21 (view B k bits 2-4)
    bflyp<2>(p, CF1(19), SF1(19));
    bflyp<3>(p, CF1(20), SF1(20));
    bflyp<4>(p, CF1(21), SF1(21));

    // ---- diagonal sign (layer-independent mask)
#pragma unroll
    for (int i = 0; i < 16; i++) {
        unsigned lo = cbase ^ ((akk >> (2 * i)) & 1u) ^ par((unsigned)(2 * i) & km);
        unsigned hi = cbase ^ ((akk >> (2 * i + 1)) & 1u) ^ par((unsigned)(2 * i + 1) & km);
        p[i] ^= ((ull)hi << 63) | ((ull)lo << 31);
    }

    // stage S2 global bits 19-21
    bflyp<2>(p, CF2(19), SF2(19));
    bflyp<3>(p, CF2(20), SF2(20));
    bflyp<4>(p, CF2(21), SF2(21));

    // exchange B -> A (per-thread write set == read set: no pre-barrier)
#pragma unroll
    for (int i = 0; i < 16; i++) {
        float2 v = upk2(p[i]);
        sm[((((2 * i) << 3) | hv) << 6) | tl] = v.x;
        sm[((((2 * i + 1) << 3) | hv) << 6) | tl] = v.y;
    }
    __syncthreads();
#pragma unroll
    for (int i = 0; i < 16; i++)
        p[i] = pk2(sm[(((hv << 5) | (2 * i)) << 6) | tl],
                   sm[(((hv << 5) | (2 * i + 1)) << 6) | tl]);

    // stage S2 global bits 14-18
    bflyp<0>(p, CF2(14), SF2(14));
    bflyp<1>(p, CF2(15), SF2(15));
    bflyp<2>(p, CF2(16), SF2(16));
    bflyp<3>(p, CF2(17), SF2(17));
    bflyp<4>(p, CF2(18), SF2(18));

#pragma unroll
    for (int i = 0; i < 16; i++) {
        float2 v = upk2(p[i]);
        g_state[(((hv << 5) | (2 * i)) << LOWB) | low] = v.x;
        g_state[(((hv << 5) | (2 * i + 1)) << LOWB) | low] = v.y;
    }
#undef CF1
#undef SF1
#undef CF2
#undef SF2
}

// ---------------------------------------------------------------- K4 passH1
// sign at load (view A: h = (hv<<5)|k, k bits = global 14-18) + stage S hi RYs.
template <int S>
__global__ void __launch_bounds__(512, 2) k_passH1() {
    extern __shared__ float sm[];
    const int t = threadIdx.x;
    const int lane = t & 31;
    float myc = lane < NQ ? g_c[S][lane] : 0.f;
    float mys = lane < NQ ? g_s[S][lane] : 0.f;
#define CF(b) __shfl_sync(FULL, myc, (b))
#define SF(b) __shfl_sync(FULL, mys, (b))

    const int tl = t & 63;
    const unsigned hv = t >> 6;          // hhi (h bits 5-7)
    const int low = (blockIdx.x << 6) + tl;
    const unsigned ulow = (unsigned)low;

    // ---- sign constants for VIEW A
    unsigned Bb = signB(ulow);
    unsigned cl = signCL(ulow);
    unsigned chm = 0;
#pragma unroll
    for (int a = 0; a < 5; a++)
        chm |= par(hv & ((g_pm[14 + a] >> 19) & 7u)) << a;
    unsigned Ahh = 0;
#pragma unroll
    for (int a = 1; a < 3; a++)
        Ahh ^= ((hv >> a) & 1u) & par(hv & ((g_pm[19 + a] >> 19) & ((1u << a) - 1u)));
    unsigned ab = 0;
#pragma unroll
    for (int a = 1; a < 5; a++)
        ab ^= (((unsigned)lane >> a) & 1u) &
              par((unsigned)lane & ((g_pm[14 + a] >> 14) & ((1u << a) - 1u)));
    const unsigned akk = __ballot_sync(FULL, ab);
    const unsigned km = (cl & 31u) ^ chm;
    const unsigned cbase = Bb ^ par(hv & (cl >> 5)) ^ Ahh;

    ull p[16];
#pragma unroll
    for (int i = 0; i < 16; i++) {
        float lo = g_state[(((hv << 5) | (2 * i)) << LOWB) | low];
        float hi = g_state[(((hv << 5) | (2 * i + 1)) << LOWB) | low];
        p[i] = pk2(lo, hi);
    }
#pragma unroll
    for (int i = 0; i < 16; i++) {
        unsigned lo = cbase ^ ((akk >> (2 * i)) & 1u) ^ par((unsigned)(2 * i) & km);
        unsigned hi = cbase ^ ((akk >> (2 * i + 1)) & 1u) ^ par((unsigned)(2 * i + 1) & km);
        p[i] ^= ((ull)hi << 63) | ((ull)lo << 31);
    }

    // stage S global bits 14-18
    bflyp<0>(p, CF(14), SF(14));
    bflyp<1>(p, CF(15), SF(15));
    bflyp<2>(p, CF(16), SF(16));
    bflyp<3>(p, CF(17), SF(17));
    bflyp<4>(p, CF(18), SF(18));

    // exchange A -> B
#pragma unroll
    for (int i = 0; i < 16; i++) {
        float2 v = upk2(p[i]);
        sm[(((hv << 5) | (2 * i)) << 6) | tl] = v.x;
        sm[(((hv << 5) | (2 * i + 1)) << 6) | tl] = v.y;
    }
    __syncthreads();
#pragma unroll
    for (int i = 0; i < 16; i++)
        p[i] = pk2(sm[((((2 * i) << 3) | hv) << 6) | tl],
                   sm[((((2 * i + 1) << 3) | hv) << 6) | tl]);

    // stage S global bits 19-21 (view B k bits 2-4)
    bflyp<2>(p, CF(19), SF(19));
    bflyp<3>(p, CF(20), SF(20));
    bflyp<4>(p, CF(21), SF(21));

#pragma unroll
    for (int i = 0; i < 16; i++) {
        float2 v = upk2(p[i]);
        g_state[((((2 * i) << 3) | hv) << LOWB) | low] = v.x;
        g_state[((((2 * i + 1) << 3) | hv) << LOWB) | low] = v.y;
    }
#undef CF
#undef SF
}

// ---------------------------------------------------------------- pass L
// bits 0..13 within a contiguous 16384 block. Pair-preserving swizzle:
// lw(x) = x ^ (((x>>5)&15)<<1)  (bit0 untouched -> STS.64 pairs stay ordered).
// Conflict check: A store/load bank = (k ^ ((t&15)<<1)) half-warp distinct as
// 64-bit; B bank = (t&31)^((k&15)<<1) lane-distinct; C bank = lane ^ const.
__device__ __forceinline__ int lw(int x) { return x ^ (((x >> 5) & 15) << 1); }

template <int STAGE, bool INIT, bool LAST>
__global__ void __launch_bounds__(512, 2) k_passL(float* __restrict__ out) {
    extern __shared__ float sm[];
    __shared__ float acc[NQ];
    const int t = threadIdx.x;
    const int lane = t & 31;
    const int base = blockIdx.x << LOWB;
    float myc = lane < NQ ? g_c[STAGE][lane] : 0.f;
    float mys = lane < NQ ? g_s[STAGE][lane] : 0.f;
#define CF(b) __shfl_sync(FULL, myc, (b))
#define SF(b) __shfl_sync(FULL, mys, (b))
    ull p[16];

    if (LAST && t < NQ) acc[t] = 0.0f;

    if (INIT) {
        float c0 = lane < NQ ? g_c[0][lane] : 0.f;
        float s0 = lane < NQ ? g_s[0][lane] : 0.f;
        float a = 1.0f;
        const unsigned blk = blockIdx.x;     // bits 14-21
#pragma unroll
        for (int b = 0; b < 8; b++) {
            float cb = __shfl_sync(FULL, c0, 14 + b);
            float sb = __shfl_sync(FULL, s0, 14 + b);
            a *= ((blk >> b) & 1) ? sb : cb;
        }
#pragma unroll
        for (int b = 0; b < 9; b++) {        // bits 5-13 = t
            float cb = __shfl_sync(FULL, c0, 5 + b);
            float sb = __shfl_sync(FULL, s0, 5 + b);
            a *= ((t >> b) & 1) ? sb : cb;
        }
        float pc[5], ps[5];
#pragma unroll
        for (int b = 0; b < 5; b++) {
            pc[b] = __shfl_sync(FULL, c0, b);
            ps[b] = __shfl_sync(FULL, s0, b);
        }
#pragma unroll
        for (int i = 0; i < 16; i++) {
            float alo = a, ahi = a;
#pragma unroll
            for (int b = 1; b < 5; b++) {
                float f = (((2 * i) >> b) & 1) ? ps[b] : pc[b];
                alo *= f; ahi *= f;
            }
            p[i] = pk2(alo * pc[0], ahi * ps[0]);
        }
    } else {
        const ulonglong2* gp =
            reinterpret_cast<const ulonglong2*>(&g_state[base + t * 32]);
#pragma unroll
        for (int i = 0; i < 8; i++) {
            ulonglong2 q = gp[i];
            p[2 * i] = q.x;
            p[2 * i + 1] = q.y;
        }
    }

    // ---- A: regs own bits 0-4
    bflyp<0>(p, CF(0), SF(0));
    bflyp<1>(p, CF(1), SF(1));
    bflyp<2>(p, CF(2), SF(2));
    bflyp<3>(p, CF(3), SF(3));
    bflyp<4>(p, CF(4), SF(4));

#pragma unroll
    for (int i = 0; i < 16; i++)
        *reinterpret_cast<ull*>(&sm[lw((t << 5) | (2 * i))]) = p[i];
    __syncthreads();

    // ---- B: regs own bits 5-9 (bfly 5-8); fixed bits 0-4 = t&31, 10-13 = t>>5
    {
        const int xb = (t & 31) | ((t >> 5) << 10);
#pragma unroll
        for (int i = 0; i < 16; i++)
            p[i] = pk2(sm[lw(xb | ((2 * i) << 5))],
                       sm[lw(xb | ((2 * i + 1) << 5))]);

        bflyp<0>(p, CF(5), SF(5));
        bflyp<1>(p, CF(6), SF(6));
        bflyp<2>(p, CF(7), SF(7));
        bflyp<3>(p, CF(8), SF(8));

#pragma unroll
        for (int i = 0; i < 16; i++) {
            float2 v = upk2(p[i]);
            sm[lw(xb | ((2 * i) << 5))] = v.x;
            sm[lw(xb | ((2 * i + 1) << 5))] = v.y;
        }
    }
    __syncthreads();

    // ---- C: regs own bits 9-13; fixed bits 0-8 = t
#pragma unroll
    for (int i = 0; i < 16; i++)
        p[i] = pk2(sm[lw(t | ((2 * i) << 9))],
                   sm[lw(t | ((2 * i + 1) << 9))]);

    bflyp<0>(p, CF(9),  SF(9));
    bflyp<1>(p, CF(10), SF(10));
    bflyp<2>(p, CF(11), SF(11));
    bflyp<3>(p, CF(12), SF(12));
    bflyp<4>(p, CF(13), SF(13));

    if (!LAST) {
#pragma unroll
        for (int i = 0; i < 16; i++) {
            float2 v = upk2(p[i]);
            g_state[base | ((2 * i) << 9) | t] = v.x;
            g_state[base | ((2 * i + 1) << 9) | t] = v.y;
        }
    } else {
        // fused expectation values. x bits: 0-4 lane, 5-8 warp, 9-13 k, 14-21 blk.
        float P = 0.f, S0 = 0.f, S1 = 0.f, S2 = 0.f, S3 = 0.f, S4 = 0.f;
#pragma unroll
        for (int i = 0; i < 16; i++) {
            float2 v = upk2(p[i]);
            float px = v.x * v.x, py = v.y * v.y;
            float pp = px + py;
            P += pp;
            S0 += px - py;                 // bit 9 = k&1
            S1 += (i & 1) ? -pp : pp;      // bit 10
            S2 += (i & 2) ? -pp : pp;      // bit 11
            S3 += (i & 4) ? -pp : pp;      // bit 12
            S4 += (i & 8) ? -pp : pp;      // bit 13
        }
        float R0 = (lane & 1)  ? -P : P;
        float R1 = (lane & 2)  ? -P : P;
        float R2 = (lane & 4)  ? -P : P;
        float R3 = (lane & 8)  ? -P : P;
        float R4 = (lane & 16) ? -P : P;
#pragma unroll
        for (int o = 16; o; o >>= 1) {
            P  += __shfl_xor_sync(FULL, P, o);
            S0 += __shfl_xor_sync(FULL, S0, o);
            S1 += __shfl_xor_sync(FULL, S1, o);
            S2 += __shfl_xor_sync(FULL, S2, o);
            S3 += __shfl_xor_sync(FULL, S3, o);
            S4 += __shfl_xor_sync(FULL, S4, o);
            R0 += __shfl_xor_sync(FULL, R0, o);
            R1 += __shfl_xor_sync(FULL, R1, o);
            R2 += __shfl_xor_sync(FULL, R2, o);
            R3 += __shfl_xor_sync(FULL, R3, o);
            R4 += __shfl_xor_sync(FULL, R4, o);
        }
        if (lane == 0) {
            int wrp = t >> 5;
            atomicAdd(&acc[0], R0);
            atomicAdd(&acc[1], R1);
            atomicAdd(&acc[2], R2);
            atomicAdd(&acc[3], R3);
            atomicAdd(&acc[4], R4);
#pragma unroll
            for (int b = 5; b < 9; b++)
                atomicAdd(&acc[b], ((wrp >> (b - 5)) & 1) ? -P : P);
            atomicAdd(&acc[9],  S0);
            atomicAdd(&acc[10], S1);
            atomicAdd(&acc[11], S2);
            atomicAdd(&acc[12], S3);
            atomicAdd(&acc[13], S4);
#pragma unroll
            for (int b = 14; b < NQ; b++)
                atomicAdd(&acc[b], ((blockIdx.x >> (b - 14)) & 1) ? -P : P);
        }
        __syncthreads();
        if (t < NQ) atomicAdd(&out[NQ - 1 - t], acc[t]);
    }
#undef CF
#undef SF
}

// ---------------------------------------------------------------- launch
extern "C" void kernel_launch(void* const* d_in, const int* in_sizes, int n_in,
                              void* d_out, int out_size) {
    const float* feat = (const float*)d_in[0];
    const float* adj = (const float*)d_in[1];
    const float* params = (const float*)d_in[2];
    float* out = (float*)d_out;

    const int SMEM = LOWDIM * (int)sizeof(float);   // 65536
    cudaFuncSetAttribute(k_passL<1, true,  false>, cudaFuncAttributeMaxDynamicSharedMemorySize, SMEM);
    cudaFuncSetAttribute(k_passHH<1, 2>,           cudaFuncAttributeMaxDynamicSharedMemorySize, SMEM);
    cudaFuncSetAttribute(k_passL<2, false, false>, cudaFuncAttributeMaxDynamicSharedMemorySize, SMEM);
    cudaFuncSetAttribute(k_passH1<3>,              cudaFuncAttributeMaxDynamicSharedMemorySize, SMEM);
    cudaFuncSetAttribute(k_passL<3, false, true>,  cudaFuncAttributeMaxDynamicSharedMemorySize, SMEM);

    k_setup<<<1, 128>>>(feat, adj, params, out);

    k_passL<1, true,  false><<<DIM / LOWDIM, 512, SMEM>>>(out);
    k_passHH<1, 2>          <<<LOWDIM / 64, 512, SMEM>>>();
    k_passL<2, false, false><<<DIM / LOWDIM, 512, SMEM>>>(out);
    k_passH1<3>             <<<LOWDIM / 64, 512, SMEM>>>();
    k_passL<3, false, true> <<<DIM / LOWDIM, 512, SMEM>>>(out);
}